// round 1
// baseline (speedup 1.0000x reference)
#include <cuda_runtime.h>
#include <cstddef>

#define SEQ    2048
#define BATCH  2
#define DMODEL 1024
#define NHEADS 16
#define DHEAD  64
#define MROWS  (BATCH*SEQ)

// Scratch (allocation-free rule: device globals)
__device__ float g_XB[(size_t)MROWS*DMODEL];
__device__ float g_Q [(size_t)MROWS*DMODEL];
__device__ float g_K [(size_t)MROWS*DMODEL];
__device__ float g_V [(size_t)MROWS*DMODEL];
__device__ float g_AO[(size_t)MROWS*DMODEL];
__device__ float g_O1[(size_t)MROWS*DMODEL];

// ---------------------------------------------------------------------------
// SGEMM: C[M,1024] = A[M,1024] @ B   (TRANS=false: B row-major [K,N], no scale)
//        C[m,n] = sum_k A[m,k]*scale[k]*B[n,k]  (TRANS=true: B as [N,K], scaled)
// 128x128 tile, BK=8, 256 threads, 8x8 per-thread microtile.
// ---------------------------------------------------------------------------
template<bool TRANS>
__global__ __launch_bounds__(256, 2)
void sgemm_kernel(const float* __restrict__ A, const float* __restrict__ B,
                  const float* __restrict__ scale, float* __restrict__ C)
{
    constexpr int BM = 128, BN = 128, BK = 8;
    __shared__ float As[BK][BM];
    __shared__ float Bs[BK][BN];

    const int tid  = threadIdx.x;
    const int bm   = blockIdx.y * BM;
    const int bn   = blockIdx.x * BN;
    const int trow = tid / 16;         // 0..15
    const int tcol = tid % 16;         // 0..15
    const int arow = tid >> 1;         // 0..127
    const int acol = (tid & 1) * 4;    // 0 or 4
    const int bkr  = tid >> 5;         // 0..7
    const int bcol = (tid & 31) * 4;   // 0..124

    float acc[8][8] = {};

    for (int k0 = 0; k0 < DMODEL; k0 += BK) {
        // A tile (transposed into As[k][m]), scaled on load for TRANS path
        float4 a = *reinterpret_cast<const float4*>(
            A + (size_t)(bm + arow) * DMODEL + k0 + acol);
        if (TRANS) {
            a.x *= scale[k0 + acol + 0];
            a.y *= scale[k0 + acol + 1];
            a.z *= scale[k0 + acol + 2];
            a.w *= scale[k0 + acol + 3];
        }
        As[acol + 0][arow] = a.x;
        As[acol + 1][arow] = a.y;
        As[acol + 2][arow] = a.z;
        As[acol + 3][arow] = a.w;

        if (!TRANS) {
            float4 b = *reinterpret_cast<const float4*>(
                B + (size_t)(k0 + bkr) * DMODEL + bn + bcol);
            *reinterpret_cast<float4*>(&Bs[bkr][bcol]) = b;
        } else {
            float4 b = *reinterpret_cast<const float4*>(
                B + (size_t)(bn + arow) * DMODEL + k0 + acol);
            Bs[acol + 0][arow] = b.x;
            Bs[acol + 1][arow] = b.y;
            Bs[acol + 2][arow] = b.z;
            Bs[acol + 3][arow] = b.w;
        }
        __syncthreads();

        #pragma unroll
        for (int kk = 0; kk < BK; kk++) {
            float rm[8], rn[8];
            *reinterpret_cast<float4*>(rm)     = *reinterpret_cast<const float4*>(&As[kk][trow * 8]);
            *reinterpret_cast<float4*>(rm + 4) = *reinterpret_cast<const float4*>(&As[kk][trow * 8 + 4]);
            *reinterpret_cast<float4*>(rn)     = *reinterpret_cast<const float4*>(&Bs[kk][tcol * 8]);
            *reinterpret_cast<float4*>(rn + 4) = *reinterpret_cast<const float4*>(&Bs[kk][tcol * 8 + 4]);
            #pragma unroll
            for (int ii = 0; ii < 8; ii++)
                #pragma unroll
                for (int jj = 0; jj < 8; jj++)
                    acc[ii][jj] = fmaf(rm[ii], rn[jj], acc[ii][jj]);
        }
        __syncthreads();
    }

    #pragma unroll
    for (int ii = 0; ii < 8; ii++) {
        float* cp = C + (size_t)(bm + trow * 8 + ii) * DMODEL + bn + tcol * 8;
        float4 v0 = {acc[ii][0], acc[ii][1], acc[ii][2], acc[ii][3]};
        float4 v1 = {acc[ii][4], acc[ii][5], acc[ii][6], acc[ii][7]};
        *reinterpret_cast<float4*>(cp)     = v0;
        *reinterpret_cast<float4*>(cp + 4) = v1;
    }
}

// ---------------------------------------------------------------------------
// Causal flash attention with additive route bias.
// Block = 64 threads = 64 q rows (one (b,h,q-tile)); 32-key shared tiles.
// Online softmax in 16-key groups (registers bounded). Causal tiles skipped.
// ---------------------------------------------------------------------------
__global__ __launch_bounds__(64)
void attn_kernel(const float* __restrict__ Q, const float* __restrict__ Kc,
                 const float* __restrict__ V, const float* __restrict__ bias,
                 float* __restrict__ O)
{
    constexpr int KT = 32;
    __shared__ float ksh[KT][DHEAD + 4];   // [key][d], reads are uniform (broadcast)
    __shared__ float vsh[KT][DHEAD + 4];
    __shared__ float bsh[KT][65];          // [key][qrow], conflict-free both ways

    const int qt  = (int)gridDim.x - 1 - (int)blockIdx.x;  // heavy blocks first
    const int h   = blockIdx.y;
    const int b   = blockIdx.z;
    const int q0  = qt * 64;
    const int i   = threadIdx.x;
    const int row = q0 + i;

    float qreg[DHEAD];
    {
        const float* qp = Q + ((size_t)(b * SEQ + row)) * DMODEL + h * DHEAD;
        #pragma unroll
        for (int d = 0; d < DHEAD; d += 4) {
            float4 t = *reinterpret_cast<const float4*>(qp + d);
            qreg[d] = t.x; qreg[d + 1] = t.y; qreg[d + 2] = t.z; qreg[d + 3] = t.w;
        }
    }
    float o[DHEAD];
    #pragma unroll
    for (int d = 0; d < DHEAD; d++) o[d] = 0.f;
    float mval = -1e30f, l = 0.f;

    const int kmax = q0 + 64;                       // causal bound for this tile
    const float* bp = bias + ((size_t)h * SEQ + row) * SEQ;

    for (int k0 = 0; k0 < kmax; k0 += KT) {
        __syncthreads();
        {   // threads 0..31 load K rows, 32..63 load V rows
            const int j = i & 31;
            const float* src = ((i < 32) ? Kc : V)
                             + ((size_t)(b * SEQ + k0 + j)) * DMODEL + h * DHEAD;
            float* dst = (i < 32) ? ksh[j] : vsh[j];
            #pragma unroll
            for (int d = 0; d < DHEAD; d += 4) {
                float4 t = *reinterpret_cast<const float4*>(src + d);
                dst[d] = t.x; dst[d + 1] = t.y; dst[d + 2] = t.z; dst[d + 3] = t.w;
            }
        }
        // bias tile, stored transposed: bsh[key][qrow]
        #pragma unroll
        for (int j = 0; j < KT; j += 4) {
            float4 t = *reinterpret_cast<const float4*>(bp + k0 + j);
            bsh[j][i] = t.x; bsh[j + 1][i] = t.y; bsh[j + 2][i] = t.z; bsh[j + 3][i] = t.w;
        }
        __syncthreads();

        #pragma unroll 1
        for (int g = 0; g < KT; g += 16) {
            float s[16];
            #pragma unroll
            for (int j = 0; j < 16; j++) {
                const int jj = g + j;
                float acc = 0.f;
                #pragma unroll
                for (int d = 0; d < DHEAD; d++)
                    acc = fmaf(qreg[d], ksh[jj][d], acc);
                s[j] = (k0 + jj <= row) ? fmaf(acc, 0.125f, bsh[jj][i]) : -1e30f;
            }
            float mnew = mval;
            #pragma unroll
            for (int j = 0; j < 16; j++) mnew = fmaxf(mnew, s[j]);
            const float corr = __expf(mval - mnew);
            l *= corr;
            #pragma unroll
            for (int d = 0; d < DHEAD; d++) o[d] *= corr;
            #pragma unroll
            for (int j = 0; j < 16; j++) {
                const float p = __expf(s[j] - mnew);
                l += p;
                #pragma unroll
                for (int d = 0; d < DHEAD; d++)
                    o[d] = fmaf(p, vsh[g + j][d], o[d]);
            }
            mval = mnew;
        }
    }

    const float inv = 1.f / l;
    float* op = O + ((size_t)(b * SEQ + row)) * DMODEL + h * DHEAD;
    #pragma unroll
    for (int d = 0; d < DHEAD; d += 4) {
        float4 t = {o[d] * inv, o[d + 1] * inv, o[d + 2] * inv, o[d + 3] * inv};
        *reinterpret_cast<float4*>(op + d) = t;
    }
}

// ---------------------------------------------------------------------------
extern "C" void kernel_launch(void* const* d_in, const int* in_sizes, int n_in,
                              void* d_out, int out_size)
{
    const float* x     = (const float*)d_in[0];
    const float* basis = (const float*)d_in[1];
    const float* sq    = (const float*)d_in[2];
    const float* sk    = (const float*)d_in[3];
    const float* sv    = (const float*)d_in[4];
    const float* so    = (const float*)d_in[5];
    const float* bias  = (const float*)d_in[6];
    float*       out   = (float*)d_out;

    float *XB, *Qm, *Km, *Vm, *AO, *O1;
    cudaGetSymbolAddress((void**)&XB, g_XB);
    cudaGetSymbolAddress((void**)&Qm, g_Q);
    cudaGetSymbolAddress((void**)&Km, g_K);
    cudaGetSymbolAddress((void**)&Vm, g_V);
    cudaGetSymbolAddress((void**)&AO, g_AO);
    cudaGetSymbolAddress((void**)&O1, g_O1);

    const dim3 gg(DMODEL / 128, MROWS / 128);

    // XB = X @ basis   (shared by q/k/v projections)
    sgemm_kernel<false><<<gg, 256>>>(x,  basis, nullptr, XB);
    // Q/K/V = (XB * s) @ basis^T
    sgemm_kernel<true ><<<gg, 256>>>(XB, basis, sq, Qm);
    sgemm_kernel<true ><<<gg, 256>>>(XB, basis, sk, Km);
    sgemm_kernel<true ><<<gg, 256>>>(XB, basis, sv, Vm);
    // causal attention with bias
    attn_kernel<<<dim3(SEQ / 64, NHEADS, BATCH), 64>>>(Qm, Km, Vm, bias, AO);
    // out = ((AO @ basis) * so) @ basis^T
    sgemm_kernel<false><<<gg, 256>>>(AO, basis, nullptr, O1);
    sgemm_kernel<true ><<<gg, 256>>>(O1, basis, so, out);
}

// round 3
// speedup vs baseline: 2.1650x; 2.1650x over previous
#include <cuda_runtime.h>
#include <cuda_bf16.h>
#include <cstdint>
#include <cstddef>

#define SEQ    2048
#define BATCH  2
#define DMODEL 1024
#define NHEADS 16
#define DHEAD  64
#define MROWS  (BATCH*SEQ)

// Scratch (allocation-free rule: device globals)
__device__ float g_XB[(size_t)MROWS*DMODEL];
__device__ float g_Q [(size_t)MROWS*DMODEL];
__device__ float g_K [(size_t)MROWS*DMODEL];
__device__ float g_V [(size_t)MROWS*DMODEL];
__device__ float g_AO[(size_t)MROWS*DMODEL];
__device__ float g_O1[(size_t)MROWS*DMODEL];
__device__ float g_basisT[(size_t)DMODEL*DMODEL];

// ---------------------------------------------------------------------------
__device__ __forceinline__ uint32_t smem_u32(const void* p) {
    uint32_t a;
    asm("{ .reg .u64 t; cvta.to.shared.u64 t, %1; cvt.u32.u64 %0, t; }"
        : "=r"(a) : "l"(p));
    return a;
}

#define LDMX4(r0, r1, r2, r3, addr) \
    asm volatile("ldmatrix.sync.aligned.m8n8.x4.shared.b16 {%0,%1,%2,%3}, [%4];" \
                 : "=r"(r0), "=r"(r1), "=r"(r2), "=r"(r3) : "r"(addr))

#define MMA16816(d, a, b) \
    asm volatile("mma.sync.aligned.m16n8k16.row.col.f32.bf16.bf16.f32 " \
                 "{%0,%1,%2,%3}, {%4,%5,%6,%7}, {%8,%9}, {%0,%1,%2,%3};" \
                 : "+f"((d)[0]), "+f"((d)[1]), "+f"((d)[2]), "+f"((d)[3]) \
                 : "r"((a)[0]), "r"((a)[1]), "r"((a)[2]), "r"((a)[3]), \
                   "r"((b)[0]), "r"((b)[1]))

// fp32x4 -> bf16 hi/lo split, two 8-byte stores
__device__ __forceinline__ void split_store(void* hp, void* lp, float4 v) {
    __nv_bfloat16 h0 = __float2bfloat16(v.x), h1 = __float2bfloat16(v.y);
    __nv_bfloat16 h2 = __float2bfloat16(v.z), h3 = __float2bfloat16(v.w);
    __nv_bfloat16 l0 = __float2bfloat16(v.x - __bfloat162float(h0));
    __nv_bfloat16 l1 = __float2bfloat16(v.y - __bfloat162float(h1));
    __nv_bfloat16 l2 = __float2bfloat16(v.z - __bfloat162float(h2));
    __nv_bfloat16 l3 = __float2bfloat16(v.w - __bfloat162float(h3));
    uint2 hu, lu;
    hu.x = (uint32_t)__bfloat16_as_ushort(h0) | ((uint32_t)__bfloat16_as_ushort(h1) << 16);
    hu.y = (uint32_t)__bfloat16_as_ushort(h2) | ((uint32_t)__bfloat16_as_ushort(h3) << 16);
    lu.x = (uint32_t)__bfloat16_as_ushort(l0) | ((uint32_t)__bfloat16_as_ushort(l1) << 16);
    lu.y = (uint32_t)__bfloat16_as_ushort(l2) | ((uint32_t)__bfloat16_as_ushort(l3) << 16);
    *reinterpret_cast<uint2*>(hp) = hu;
    *reinterpret_cast<uint2*>(lp) = lu;
}

// ---------------------------------------------------------------------------
// bf16x3 mma.sync GEMM: C[m,n] = sum_k A[m,k]*(scale[k])*B[n,k]
// B given [N,K] row-major (K-major). Tile 128x128, BK=32, 2-stage smem.
// Row stride 40 bf16 (80B): 8 consecutive rows hit 8 distinct 16B chunks.
// ---------------------------------------------------------------------------
static constexpr int RS = 40;                       // row stride in bf16 elems
static constexpr int TILE_E  = 128 * RS;            // 5120 elems per matrix tile
static constexpr int STAGE_E = 4 * TILE_E;          // Ah, Al, Bh, Bl
static constexpr int SMEM_DYN = 2 * STAGE_E * 2;    // bytes = 81920

template<bool SCALED>
__global__ __launch_bounds__(256, 1)
void sgemm_mma(const float* __restrict__ A, const float* __restrict__ B,
               const float* __restrict__ scale, float* __restrict__ C)
{
    extern __shared__ __nv_bfloat16 smem[];
    const int tid  = threadIdx.x;
    const int lane = tid & 31;
    const int wid  = tid >> 5;
    const int bm   = blockIdx.y * 128;
    const int bn   = blockIdx.x * 128;
    const int wm0  = (wid & 3) * 32;     // warp m offset
    const int wn0  = (wid >> 2) * 64;    // warp n offset

    const uint32_t smem_base = smem_u32(smem);

    // gmem load geometry: 4 float4 per thread per 128x32 tile
    const int grow = tid >> 3;           // 0..31 base row
    const int gc4  = (tid & 7) * 4;      // fp32 column within chunk

    float4 pa[4], pb[4];
    float acc[2][8][4];
    #pragma unroll
    for (int i = 0; i < 2; ++i)
        #pragma unroll
        for (int j = 0; j < 8; ++j)
            #pragma unroll
            for (int q = 0; q < 4; ++q) acc[i][j][q] = 0.f;

    auto load_chunk = [&](int c) {
        const int k0 = c * 32;
        const float* Ap = A + (size_t)(bm + grow) * DMODEL + k0 + gc4;
        const float* Bp = B + (size_t)(bn + grow) * DMODEL + k0 + gc4;
        #pragma unroll
        for (int i = 0; i < 4; ++i) pa[i] = *reinterpret_cast<const float4*>(Ap + (size_t)i * 32 * DMODEL);
        #pragma unroll
        for (int i = 0; i < 4; ++i) pb[i] = *reinterpret_cast<const float4*>(Bp + (size_t)i * 32 * DMODEL);
        if (SCALED) {
            float4 sc = *reinterpret_cast<const float4*>(scale + k0 + gc4);
            #pragma unroll
            for (int i = 0; i < 4; ++i) {
                pa[i].x *= sc.x; pa[i].y *= sc.y; pa[i].z *= sc.z; pa[i].w *= sc.w;
            }
        }
    };

    auto store_chunk = [&](int s) {
        __nv_bfloat16* Ah = smem + s * STAGE_E;
        __nv_bfloat16* Al = Ah + TILE_E;
        __nv_bfloat16* Bh = Ah + 2 * TILE_E;
        __nv_bfloat16* Bl = Ah + 3 * TILE_E;
        #pragma unroll
        for (int i = 0; i < 4; ++i) {
            const int off = (grow + i * 32) * RS + gc4;
            split_store(Ah + off, Al + off, pa[i]);
            split_store(Bh + off, Bl + off, pb[i]);
        }
    };

    auto compute = [&](int s) {
        const uint32_t st = smem_base + s * (STAGE_E * 2);   // bytes
        const uint32_t Ah_u = st;
        const uint32_t Al_u = st + TILE_E * 2;
        const uint32_t Bh_u = st + 2 * TILE_E * 2;
        const uint32_t Bl_u = st + 3 * TILE_E * 2;
        #pragma unroll
        for (int ks = 0; ks < 2; ++ks) {
            const int k0 = ks * 16;
            uint32_t ah[2][4], al[2][4], bh[8][2], bl[8][2];
            #pragma unroll
            for (int mt = 0; mt < 2; ++mt) {
                const uint32_t off =
                    ((wm0 + mt * 16 + (lane & 15)) * RS + k0 + ((lane >> 4) << 3)) * 2;
                LDMX4(ah[mt][0], ah[mt][1], ah[mt][2], ah[mt][3], Ah_u + off);
                LDMX4(al[mt][0], al[mt][1], al[mt][2], al[mt][3], Al_u + off);
            }
            #pragma unroll
            for (int bb = 0; bb < 4; ++bb) {
                const int n0 = wn0 + bb * 16;
                const uint32_t off =
                    ((n0 + (lane & 7) + ((lane >> 4) << 3)) * RS + k0 + (lane & 8)) * 2;
                LDMX4(bh[2 * bb][0], bh[2 * bb][1], bh[2 * bb + 1][0], bh[2 * bb + 1][1], Bh_u + off);
                LDMX4(bl[2 * bb][0], bl[2 * bb][1], bl[2 * bb + 1][0], bl[2 * bb + 1][1], Bl_u + off);
            }
            #pragma unroll
            for (int mt = 0; mt < 2; ++mt)
                #pragma unroll
                for (int nf = 0; nf < 8; ++nf) {
                    MMA16816(acc[mt][nf], ah[mt], bh[nf]);
                    MMA16816(acc[mt][nf], ah[mt], bl[nf]);
                    MMA16816(acc[mt][nf], al[mt], bh[nf]);
                }
        }
    };

    load_chunk(0);
    store_chunk(0);
    __syncthreads();

    for (int c = 0; c < 32; ++c) {
        if (c < 31) load_chunk(c + 1);
        compute(c & 1);
        __syncthreads();
        if (c < 31) {
            store_chunk((c + 1) & 1);
            __syncthreads();
        }
    }

    // Epilogue: c-frag -> fp32 gmem
    #pragma unroll
    for (int mt = 0; mt < 2; ++mt) {
        const int m = bm + wm0 + mt * 16 + (lane >> 2);
        #pragma unroll
        for (int nf = 0; nf < 8; ++nf) {
            const int n = bn + wn0 + nf * 8 + (lane & 3) * 2;
            float2 v0 = {acc[mt][nf][0], acc[mt][nf][1]};
            float2 v1 = {acc[mt][nf][2], acc[mt][nf][3]};
            *reinterpret_cast<float2*>(C + (size_t)m * DMODEL + n) = v0;
            *reinterpret_cast<float2*>(C + (size_t)(m + 8) * DMODEL + n) = v1;
        }
    }
}

// ---------------------------------------------------------------------------
// basis transpose (for NN GEMMs): out[n][k] = in[k][n]
// ---------------------------------------------------------------------------
__global__ void transpose_k(const float* __restrict__ in, float* __restrict__ out) {
    __shared__ float t[32][33];
    int bx = blockIdx.x * 32, by = blockIdx.y * 32;
    int x = bx + threadIdx.x;
    #pragma unroll
    for (int i = 0; i < 32; i += 8)
        t[threadIdx.y + i][threadIdx.x] = in[(size_t)(by + threadIdx.y + i) * DMODEL + x];
    __syncthreads();
    x = by + threadIdx.x;
    #pragma unroll
    for (int i = 0; i < 32; i += 8)
        out[(size_t)(bx + threadIdx.y + i) * DMODEL + x] = t[threadIdx.x][threadIdx.y + i];
}

// ---------------------------------------------------------------------------
// Causal flash attention with additive route bias (SIMT baseline, unchanged).
// ---------------------------------------------------------------------------
__global__ __launch_bounds__(64)
void attn_kernel(const float* __restrict__ Q, const float* __restrict__ Kc,
                 const float* __restrict__ V, const float* __restrict__ bias,
                 float* __restrict__ O)
{
    constexpr int KT = 32;
    __shared__ float ksh[KT][DHEAD + 4];
    __shared__ float vsh[KT][DHEAD + 4];
    __shared__ float bsh[KT][65];

    const int qt  = (int)gridDim.x - 1 - (int)blockIdx.x;
    const int h   = blockIdx.y;
    const int b   = blockIdx.z;
    const int q0  = qt * 64;
    const int i   = threadIdx.x;
    const int row = q0 + i;

    float qreg[DHEAD];
    {
        const float* qp = Q + ((size_t)(b * SEQ + row)) * DMODEL + h * DHEAD;
        #pragma unroll
        for (int d = 0; d < DHEAD; d += 4) {
            float4 t = *reinterpret_cast<const float4*>(qp + d);
            qreg[d] = t.x; qreg[d + 1] = t.y; qreg[d + 2] = t.z; qreg[d + 3] = t.w;
        }
    }
    float o[DHEAD];
    #pragma unroll
    for (int d = 0; d < DHEAD; d++) o[d] = 0.f;
    float mval = -1e30f, l = 0.f;

    const int kmax = q0 + 64;
    const float* bp = bias + ((size_t)h * SEQ + row) * SEQ;

    for (int k0 = 0; k0 < kmax; k0 += KT) {
        __syncthreads();
        {
            const int j = i & 31;
            const float* src = ((i < 32) ? Kc : V)
                             + ((size_t)(b * SEQ + k0 + j)) * DMODEL + h * DHEAD;
            float* dst = (i < 32) ? ksh[j] : vsh[j];
            #pragma unroll
            for (int d = 0; d < DHEAD; d += 4) {
                float4 t = *reinterpret_cast<const float4*>(src + d);
                dst[d] = t.x; dst[d + 1] = t.y; dst[d + 2] = t.z; dst[d + 3] = t.w;
            }
        }
        #pragma unroll
        for (int j = 0; j < KT; j += 4) {
            float4 t = *reinterpret_cast<const float4*>(bp + k0 + j);
            bsh[j][i] = t.x; bsh[j + 1][i] = t.y; bsh[j + 2][i] = t.z; bsh[j + 3][i] = t.w;
        }
        __syncthreads();

        #pragma unroll 1
        for (int g = 0; g < KT; g += 16) {
            float s[16];
            #pragma unroll
            for (int j = 0; j < 16; j++) {
                const int jj = g + j;
                float a = 0.f;
                #pragma unroll
                for (int d = 0; d < DHEAD; d++)
                    a = fmaf(qreg[d], ksh[jj][d], a);
                s[j] = (k0 + jj <= row) ? fmaf(a, 0.125f, bsh[jj][i]) : -1e30f;
            }
            float mnew = mval;
            #pragma unroll
            for (int j = 0; j < 16; j++) mnew = fmaxf(mnew, s[j]);
            const float corr = __expf(mval - mnew);
            l *= corr;
            #pragma unroll
            for (int d = 0; d < DHEAD; d++) o[d] *= corr;
            #pragma unroll
            for (int j = 0; j < 16; j++) {
                const float p = __expf(s[j] - mnew);
                l += p;
                #pragma unroll
                for (int d = 0; d < DHEAD; d++)
                    o[d] = fmaf(p, vsh[g + j][d], o[d]);
            }
            mval = mnew;
        }
    }

    const float inv = 1.f / l;
    float* op = O + ((size_t)(b * SEQ + row)) * DMODEL + h * DHEAD;
    #pragma unroll
    for (int d = 0; d < DHEAD; d += 4) {
        float4 t = {o[d] * inv, o[d + 1] * inv, o[d + 2] * inv, o[d + 3] * inv};
        *reinterpret_cast<float4*>(op + d) = t;
    }
}

// ---------------------------------------------------------------------------
extern "C" void kernel_launch(void* const* d_in, const int* in_sizes, int n_in,
                              void* d_out, int out_size)
{
    const float* x     = (const float*)d_in[0];
    const float* basis = (const float*)d_in[1];
    const float* sq    = (const float*)d_in[2];
    const float* sk    = (const float*)d_in[3];
    const float* sv    = (const float*)d_in[4];
    const float* so    = (const float*)d_in[5];
    const float* bias  = (const float*)d_in[6];
    float*       out   = (float*)d_out;

    float *XB, *Qm, *Km, *Vm, *AO, *O1, *BT;
    cudaGetSymbolAddress((void**)&XB, g_XB);
    cudaGetSymbolAddress((void**)&Qm, g_Q);
    cudaGetSymbolAddress((void**)&Km, g_K);
    cudaGetSymbolAddress((void**)&Vm, g_V);
    cudaGetSymbolAddress((void**)&AO, g_AO);
    cudaGetSymbolAddress((void**)&O1, g_O1);
    cudaGetSymbolAddress((void**)&BT, g_basisT);

    cudaFuncSetAttribute(sgemm_mma<false>, cudaFuncAttributeMaxDynamicSharedMemorySize, SMEM_DYN);
    cudaFuncSetAttribute(sgemm_mma<true >, cudaFuncAttributeMaxDynamicSharedMemorySize, SMEM_DYN);

    // basisT for NN GEMMs
    transpose_k<<<dim3(32, 32), dim3(32, 8)>>>(basis, BT);

    const dim3 gg(DMODEL / 128, MROWS / 128);
    // XB = X @ basis
    sgemm_mma<false><<<gg, 256, SMEM_DYN>>>(x,  BT,    nullptr, XB);
    // Q/K/V = (XB * s) @ basis^T
    sgemm_mma<true ><<<gg, 256, SMEM_DYN>>>(XB, basis, sq, Qm);
    sgemm_mma<true ><<<gg, 256, SMEM_DYN>>>(XB, basis, sk, Km);
    sgemm_mma<true ><<<gg, 256, SMEM_DYN>>>(XB, basis, sv, Vm);
    // attention
    attn_kernel<<<dim3(SEQ / 64, NHEADS, BATCH), 64>>>(Qm, Km, Vm, bias, AO);
    // out = ((AO @ basis) * so) @ basis^T
    sgemm_mma<false><<<gg, 256, SMEM_DYN>>>(AO, BT,    nullptr, O1);
    sgemm_mma<true ><<<gg, 256, SMEM_DYN>>>(O1, basis, so, out);
}

// round 4
// speedup vs baseline: 4.9357x; 2.2797x over previous
#include <cuda_runtime.h>
#include <cuda_bf16.h>
#include <cstdint>
#include <cstddef>

#define SEQ    2048
#define BATCH  2
#define DMODEL 1024
#define NHEADS 16
#define DHEAD  64
#define MROWS  (BATCH*SEQ)

// Scratch (allocation-free rule: device globals)
__device__ float g_XB[(size_t)MROWS*DMODEL];
__device__ float g_Q [(size_t)MROWS*DMODEL];
__device__ float g_K [(size_t)MROWS*DMODEL];
__device__ float g_V [(size_t)MROWS*DMODEL];
__device__ float g_AO[(size_t)MROWS*DMODEL];
__device__ float g_O1[(size_t)MROWS*DMODEL];
__device__ float g_basisT[(size_t)DMODEL*DMODEL];

// ---------------------------------------------------------------------------
__device__ __forceinline__ uint32_t smem_u32(const void* p) {
    uint32_t a;
    asm("{ .reg .u64 t; cvta.to.shared.u64 t, %1; cvt.u32.u64 %0, t; }"
        : "=r"(a) : "l"(p));
    return a;
}

#define LDMX4(r0, r1, r2, r3, addr) \
    asm volatile("ldmatrix.sync.aligned.m8n8.x4.shared.b16 {%0,%1,%2,%3}, [%4];" \
                 : "=r"(r0), "=r"(r1), "=r"(r2), "=r"(r3) : "r"(addr))

#define LDMX4T(r0, r1, r2, r3, addr) \
    asm volatile("ldmatrix.sync.aligned.m8n8.x4.trans.shared.b16 {%0,%1,%2,%3}, [%4];" \
                 : "=r"(r0), "=r"(r1), "=r"(r2), "=r"(r3) : "r"(addr))

#define MMA16816(d, a, b) \
    asm volatile("mma.sync.aligned.m16n8k16.row.col.f32.bf16.bf16.f32 " \
                 "{%0,%1,%2,%3}, {%4,%5,%6,%7}, {%8,%9}, {%0,%1,%2,%3};" \
                 : "+f"((d)[0]), "+f"((d)[1]), "+f"((d)[2]), "+f"((d)[3]) \
                 : "r"((a)[0]), "r"((a)[1]), "r"((a)[2]), "r"((a)[3]), \
                   "r"((b)[0]), "r"((b)[1]))

#define MMA16816_2(d, a, b0r, b1r) \
    asm volatile("mma.sync.aligned.m16n8k16.row.col.f32.bf16.bf16.f32 " \
                 "{%0,%1,%2,%3}, {%4,%5,%6,%7}, {%8,%9}, {%0,%1,%2,%3};" \
                 : "+f"((d)[0]), "+f"((d)[1]), "+f"((d)[2]), "+f"((d)[3]) \
                 : "r"((a)[0]), "r"((a)[1]), "r"((a)[2]), "r"((a)[3]), \
                   "r"(b0r), "r"(b1r))

// fp32x4 -> bf16 hi/lo split, two 8-byte stores
__device__ __forceinline__ void split_store(void* hp, void* lp, float4 v) {
    __nv_bfloat16 h0 = __float2bfloat16(v.x), h1 = __float2bfloat16(v.y);
    __nv_bfloat16 h2 = __float2bfloat16(v.z), h3 = __float2bfloat16(v.w);
    __nv_bfloat16 l0 = __float2bfloat16(v.x - __bfloat162float(h0));
    __nv_bfloat16 l1 = __float2bfloat16(v.y - __bfloat162float(h1));
    __nv_bfloat16 l2 = __float2bfloat16(v.z - __bfloat162float(h2));
    __nv_bfloat16 l3 = __float2bfloat16(v.w - __bfloat162float(h3));
    uint2 hu, lu;
    hu.x = (uint32_t)__bfloat16_as_ushort(h0) | ((uint32_t)__bfloat16_as_ushort(h1) << 16);
    hu.y = (uint32_t)__bfloat16_as_ushort(h2) | ((uint32_t)__bfloat16_as_ushort(h3) << 16);
    lu.x = (uint32_t)__bfloat16_as_ushort(l0) | ((uint32_t)__bfloat16_as_ushort(l1) << 16);
    lu.y = (uint32_t)__bfloat16_as_ushort(l2) | ((uint32_t)__bfloat16_as_ushort(l3) << 16);
    *reinterpret_cast<uint2*>(hp) = hu;
    *reinterpret_cast<uint2*>(lp) = lu;
}

__device__ __forceinline__ uint32_t packbf(float a, float b) {
    __nv_bfloat16 x = __float2bfloat16(a), y = __float2bfloat16(b);
    return (uint32_t)__bfloat16_as_ushort(x) | ((uint32_t)__bfloat16_as_ushort(y) << 16);
}

// 2^y via FMA-pipe polynomial (no MUFU). y <= ~0; accuracy ~2.4e-6 rel.
__device__ __forceinline__ float exp2p(float y) {
    y = fmaxf(y, -120.f);
    float t = y + 12582912.f;               // 1.5*2^23: round-to-int in mantissa
    int   n = (__float_as_int(t) & 0x7FFFFF) - 0x400000;
    float f = y - (t - 12582912.f);         // f in [-0.5, 0.5]
    float p = 1.3333558146e-3f;
    p = fmaf(p, f, 9.6181291076e-3f);
    p = fmaf(p, f, 5.5504108664e-2f);
    p = fmaf(p, f, 2.4022650695e-1f);
    p = fmaf(p, f, 6.9314718056e-1f);
    p = fmaf(p, f, 1.0f);
    return __int_as_float(__float_as_int(p) + (n << 23));
}

// ---------------------------------------------------------------------------
// bf16x3 mma.sync GEMM (round-3 kernel, one sync per k-chunk now)
// ---------------------------------------------------------------------------
static constexpr int RS = 40;
static constexpr int TILE_E  = 128 * RS;
static constexpr int STAGE_E = 4 * TILE_E;
static constexpr int SMEM_DYN = 2 * STAGE_E * 2;

template<bool SCALED>
__global__ __launch_bounds__(256, 1)
void sgemm_mma(const float* __restrict__ A, const float* __restrict__ B,
               const float* __restrict__ scale, float* __restrict__ C)
{
    extern __shared__ __nv_bfloat16 smem[];
    const int tid  = threadIdx.x;
    const int lane = tid & 31;
    const int wid  = tid >> 5;
    const int bm   = blockIdx.y * 128;
    const int bn   = blockIdx.x * 128;
    const int wm0  = (wid & 3) * 32;
    const int wn0  = (wid >> 2) * 64;

    const uint32_t smem_base = smem_u32(smem);
    const int grow = tid >> 3;
    const int gc4  = (tid & 7) * 4;

    float4 pa[4], pb[4];
    float acc[2][8][4];
    #pragma unroll
    for (int i = 0; i < 2; ++i)
        #pragma unroll
        for (int j = 0; j < 8; ++j)
            #pragma unroll
            for (int q = 0; q < 4; ++q) acc[i][j][q] = 0.f;

    auto load_chunk = [&](int c) {
        const int k0 = c * 32;
        const float* Ap = A + (size_t)(bm + grow) * DMODEL + k0 + gc4;
        const float* Bp = B + (size_t)(bn + grow) * DMODEL + k0 + gc4;
        #pragma unroll
        for (int i = 0; i < 4; ++i) pa[i] = *reinterpret_cast<const float4*>(Ap + (size_t)i * 32 * DMODEL);
        #pragma unroll
        for (int i = 0; i < 4; ++i) pb[i] = *reinterpret_cast<const float4*>(Bp + (size_t)i * 32 * DMODEL);
        if (SCALED) {
            float4 sc = *reinterpret_cast<const float4*>(scale + k0 + gc4);
            #pragma unroll
            for (int i = 0; i < 4; ++i) {
                pa[i].x *= sc.x; pa[i].y *= sc.y; pa[i].z *= sc.z; pa[i].w *= sc.w;
            }
        }
    };

    auto store_chunk = [&](int s) {
        __nv_bfloat16* Ah = smem + s * STAGE_E;
        __nv_bfloat16* Al = Ah + TILE_E;
        __nv_bfloat16* Bh = Ah + 2 * TILE_E;
        __nv_bfloat16* Bl = Ah + 3 * TILE_E;
        #pragma unroll
        for (int i = 0; i < 4; ++i) {
            const int off = (grow + i * 32) * RS + gc4;
            split_store(Ah + off, Al + off, pa[i]);
            split_store(Bh + off, Bl + off, pb[i]);
        }
    };

    auto compute = [&](int s) {
        const uint32_t st = smem_base + s * (STAGE_E * 2);
        const uint32_t Ah_u = st;
        const uint32_t Al_u = st + TILE_E * 2;
        const uint32_t Bh_u = st + 2 * TILE_E * 2;
        const uint32_t Bl_u = st + 3 * TILE_E * 2;
        #pragma unroll
        for (int ks = 0; ks < 2; ++ks) {
            const int k0 = ks * 16;
            uint32_t ah[2][4], al[2][4], bh[8][2], bl[8][2];
            #pragma unroll
            for (int mt = 0; mt < 2; ++mt) {
                const uint32_t off =
                    ((wm0 + mt * 16 + (lane & 15)) * RS + k0 + ((lane >> 4) << 3)) * 2;
                LDMX4(ah[mt][0], ah[mt][1], ah[mt][2], ah[mt][3], Ah_u + off);
                LDMX4(al[mt][0], al[mt][1], al[mt][2], al[mt][3], Al_u + off);
            }
            #pragma unroll
            for (int bb = 0; bb < 4; ++bb) {
                const int n0 = wn0 + bb * 16;
                const uint32_t off =
                    ((n0 + (lane & 7) + ((lane >> 4) << 3)) * RS + k0 + (lane & 8)) * 2;
                LDMX4(bh[2 * bb][0], bh[2 * bb][1], bh[2 * bb + 1][0], bh[2 * bb + 1][1], Bh_u + off);
                LDMX4(bl[2 * bb][0], bl[2 * bb][1], bl[2 * bb + 1][0], bl[2 * bb + 1][1], Bl_u + off);
            }
            #pragma unroll
            for (int mt = 0; mt < 2; ++mt)
                #pragma unroll
                for (int nf = 0; nf < 8; ++nf) {
                    MMA16816(acc[mt][nf], ah[mt], bh[nf]);
                    MMA16816(acc[mt][nf], ah[mt], bl[nf]);
                    MMA16816(acc[mt][nf], al[mt], bh[nf]);
                }
        }
    };

    load_chunk(0);
    store_chunk(0);
    __syncthreads();

    for (int c = 0; c < 32; ++c) {
        if (c < 31) load_chunk(c + 1);
        compute(c & 1);
        if (c < 31) store_chunk((c + 1) & 1);   // other buffer: race-free
        __syncthreads();
    }

    #pragma unroll
    for (int mt = 0; mt < 2; ++mt) {
        const int m = bm + wm0 + mt * 16 + (lane >> 2);
        #pragma unroll
        for (int nf = 0; nf < 8; ++nf) {
            const int n = bn + wn0 + nf * 8 + (lane & 3) * 2;
            float2 v0 = {acc[mt][nf][0], acc[mt][nf][1]};
            float2 v1 = {acc[mt][nf][2], acc[mt][nf][3]};
            *reinterpret_cast<float2*>(C + (size_t)m * DMODEL + n) = v0;
            *reinterpret_cast<float2*>(C + (size_t)(m + 8) * DMODEL + n) = v1;
        }
    }
}

// ---------------------------------------------------------------------------
__global__ void transpose_k(const float* __restrict__ in, float* __restrict__ out) {
    __shared__ float t[32][33];
    int bx = blockIdx.x * 32, by = blockIdx.y * 32;
    int x = bx + threadIdx.x;
    #pragma unroll
    for (int i = 0; i < 32; i += 8)
        t[threadIdx.y + i][threadIdx.x] = in[(size_t)(by + threadIdx.y + i) * DMODEL + x];
    __syncthreads();
    x = by + threadIdx.x;
    #pragma unroll
    for (int i = 0; i < 32; i += 8)
        out[(size_t)(bx + threadIdx.y + i) * DMODEL + x] = t[threadIdx.x][threadIdx.y + i];
}

// ---------------------------------------------------------------------------
// mma.sync flash attention, bf16x3, causal, additive bias, log2-domain softmax
// CTA: 128 q-rows (8 warps x 16), k-tiles of 64. smem: K/V hi+lo double buffer.
// ---------------------------------------------------------------------------
static constexpr int RSA     = 72;                  // 64 + 8 pad (bf16 elems)
static constexpr int AT_MAT  = 64 * RSA;            // 4608 elems: one 64x64 tile
static constexpr int AT_STG  = 4 * AT_MAT;          // Kh,Kl,Vh,Vl = 18432 elems
static constexpr int ASMEM   = 2 * AT_STG * 2;      // bytes = 73728

__global__ __launch_bounds__(256, 1)
void attn_mma(const float* __restrict__ Q, const float* __restrict__ K,
              const float* __restrict__ V, const float* __restrict__ bias,
              float* __restrict__ O)
{
    extern __shared__ __nv_bfloat16 asmem[];
    const int tid  = threadIdx.x;
    const int lane = tid & 31;
    const int w    = tid >> 5;
    const int qt   = (int)gridDim.x - 1 - (int)blockIdx.x;   // heavy first
    const int h    = blockIdx.y;
    const int b    = blockIdx.z;
    const int q0   = qt * 128;
    const uint32_t sbase = smem_u32(asmem);

    // ---- stage Q (128x64) into stage-1 region, build A-frags, then free it
    {
        const float* Qb = Q + ((size_t)(b * SEQ + q0)) * DMODEL + h * DHEAD;
        #pragma unroll
        for (int i = 0; i < 8; ++i) {
            int idx = tid + i * 256;
            int row = idx >> 4, c4 = (idx & 15) * 4;
            float4 v = *reinterpret_cast<const float4*>(Qb + (size_t)row * DMODEL + c4);
            int off = row * RSA + c4;
            split_store(asmem + AT_STG + off, asmem + AT_STG + 128 * RSA + off, v);
        }
    }
    __syncthreads();
    uint32_t qh[4][4], ql[4][4];
    #pragma unroll
    for (int ks = 0; ks < 4; ++ks) {
        const uint32_t off = ((w * 16 + (lane & 15)) * RSA + ks * 16 + ((lane >> 4) << 3)) * 2;
        LDMX4(qh[ks][0], qh[ks][1], qh[ks][2], qh[ks][3], sbase + AT_STG * 2 + off);
        LDMX4(ql[ks][0], ql[ks][1], ql[ks][2], ql[ks][3], sbase + (AT_STG + 128 * RSA) * 2 + off);
    }
    __syncthreads();

    float m0 = -1e30f, m1 = -1e30f, l0 = 0.f, l1 = 0.f;
    float o[8][4];
    #pragma unroll
    for (int j = 0; j < 8; ++j)
        #pragma unroll
        for (int q = 0; q < 4; ++q) o[j][q] = 0.f;

    const int q_r0 = q0 + w * 16 + (lane >> 2);
    const int q_r1 = q_r0 + 8;
    const float* bph = bias + (size_t)h * SEQ * SEQ;
    const int nt = 2 * qt + 2;

    const int grow = tid >> 4;            // 0..15
    const int gc4  = (tid & 15) * 4;
    float4 kreg[4], vreg[4];

    auto load_tile = [&](int kt) {
        const int k0 = kt * 64;
        const float* Kb = K + ((size_t)(b * SEQ + k0 + grow)) * DMODEL + h * DHEAD + gc4;
        const float* Vb = V + ((size_t)(b * SEQ + k0 + grow)) * DMODEL + h * DHEAD + gc4;
        #pragma unroll
        for (int i = 0; i < 4; ++i) kreg[i] = *reinterpret_cast<const float4*>(Kb + (size_t)i * 16 * DMODEL);
        #pragma unroll
        for (int i = 0; i < 4; ++i) vreg[i] = *reinterpret_cast<const float4*>(Vb + (size_t)i * 16 * DMODEL);
    };
    auto store_tile = [&](int s) {
        __nv_bfloat16* st = asmem + s * AT_STG;
        #pragma unroll
        for (int i = 0; i < 4; ++i) {
            const int off = (grow + i * 16) * RSA + gc4;
            split_store(st + off,              st + AT_MAT + off,     kreg[i]);
            split_store(st + 2 * AT_MAT + off, st + 3 * AT_MAT + off, vreg[i]);
        }
    };

    load_tile(0);
    store_tile(0);
    __syncthreads();

    for (int kt = 0; kt < nt; ++kt) {
        const int s  = kt & 1;
        const int k0 = kt * 64;
        if (kt + 1 < nt) load_tile(kt + 1);

        const uint32_t Khu = sbase + s * AT_STG * 2;
        const uint32_t Klu = Khu + AT_MAT * 2;
        const uint32_t Vhu = Khu + 2 * AT_MAT * 2;
        const uint32_t Vlu = Khu + 3 * AT_MAT * 2;

        // ---- S = Q K^T (bf16x3)
        float sacc[8][4];
        #pragma unroll
        for (int j = 0; j < 8; ++j)
            #pragma unroll
            for (int q = 0; q < 4; ++q) sacc[j][q] = 0.f;
        #pragma unroll
        for (int ks = 0; ks < 4; ++ks) {
            #pragma unroll
            for (int bb = 0; bb < 4; ++bb) {
                const uint32_t off =
                    ((bb * 16 + (lane & 7) + ((lane >> 4) << 3)) * RSA + ks * 16 + (lane & 8)) * 2;
                uint32_t h0, h1, h2, h3, e0, e1, e2, e3;
                LDMX4(h0, h1, h2, h3, Khu + off);
                LDMX4(e0, e1, e2, e3, Klu + off);
                MMA16816_2(sacc[2 * bb],     qh[ks], h0, h1);
                MMA16816_2(sacc[2 * bb],     qh[ks], e0, e1);
                MMA16816_2(sacc[2 * bb],     ql[ks], h0, h1);
                MMA16816_2(sacc[2 * bb + 1], qh[ks], h2, h3);
                MMA16816_2(sacc[2 * bb + 1], qh[ks], e2, e3);
                MMA16816_2(sacc[2 * bb + 1], ql[ks], h2, h3);
            }
        }

        // ---- scale + bias (log2 domain) + causal mask
        const bool mask = (kt >= 2 * qt);
        const float* r0p = bph + (size_t)q_r0 * SEQ + k0 + 2 * (lane & 3);
        const float* r1p = bph + (size_t)q_r1 * SEQ + k0 + 2 * (lane & 3);
        #pragma unroll
        for (int nf = 0; nf < 8; ++nf) {
            float2 b0 = *reinterpret_cast<const float2*>(r0p + nf * 8);
            float2 b1 = *reinterpret_cast<const float2*>(r1p + nf * 8);
            float v0 = fmaf(sacc[nf][0], 0.18033688f, b0.x * 1.4426950f);
            float v1 = fmaf(sacc[nf][1], 0.18033688f, b0.y * 1.4426950f);
            float v2 = fmaf(sacc[nf][2], 0.18033688f, b1.x * 1.4426950f);
            float v3 = fmaf(sacc[nf][3], 0.18033688f, b1.y * 1.4426950f);
            if (mask) {
                const int kc = k0 + nf * 8 + 2 * (lane & 3);
                if (kc     > q_r0) v0 = -1e30f;
                if (kc + 1 > q_r0) v1 = -1e30f;
                if (kc     > q_r1) v2 = -1e30f;
                if (kc + 1 > q_r1) v3 = -1e30f;
            }
            sacc[nf][0] = v0; sacc[nf][1] = v1; sacc[nf][2] = v2; sacc[nf][3] = v3;
        }

        // ---- online softmax (base 2)
        float m0n = m0, m1n = m1;
        #pragma unroll
        for (int nf = 0; nf < 8; ++nf) {
            m0n = fmaxf(m0n, fmaxf(sacc[nf][0], sacc[nf][1]));
            m1n = fmaxf(m1n, fmaxf(sacc[nf][2], sacc[nf][3]));
        }
        m0n = fmaxf(m0n, __shfl_xor_sync(0xffffffffu, m0n, 1));
        m0n = fmaxf(m0n, __shfl_xor_sync(0xffffffffu, m0n, 2));
        m1n = fmaxf(m1n, __shfl_xor_sync(0xffffffffu, m1n, 1));
        m1n = fmaxf(m1n, __shfl_xor_sync(0xffffffffu, m1n, 2));
        const float c0 = exp2p(m0 - m0n), c1 = exp2p(m1 - m1n);
        m0 = m0n; m1 = m1n;
        l0 *= c0;  l1 *= c1;
        #pragma unroll
        for (int nf = 0; nf < 8; ++nf) {
            o[nf][0] *= c0; o[nf][1] *= c0;
            o[nf][2] *= c1; o[nf][3] *= c1;
        }

        uint32_t pA0[8], pA1[8], pL0[8], pL1[8];
        #pragma unroll
        for (int nf = 0; nf < 8; ++nf) {
            float p0 = exp2p(sacc[nf][0] - m0);
            float p1 = exp2p(sacc[nf][1] - m0);
            float p2 = exp2p(sacc[nf][2] - m1);
            float p3 = exp2p(sacc[nf][3] - m1);
            l0 += p0 + p1; l1 += p2 + p3;
            __nv_bfloat16 h0 = __float2bfloat16(p0), h1 = __float2bfloat16(p1);
            __nv_bfloat16 h2 = __float2bfloat16(p2), h3 = __float2bfloat16(p3);
            pA0[nf] = (uint32_t)__bfloat16_as_ushort(h0) | ((uint32_t)__bfloat16_as_ushort(h1) << 16);
            pA1[nf] = (uint32_t)__bfloat16_as_ushort(h2) | ((uint32_t)__bfloat16_as_ushort(h3) << 16);
            pL0[nf] = packbf(p0 - __bfloat162float(h0), p1 - __bfloat162float(h1));
            pL1[nf] = packbf(p2 - __bfloat162float(h2), p3 - __bfloat162float(h3));
        }

        // ---- O += P V (bf16x3), V via ldmatrix.trans
        #pragma unroll
        for (int ks = 0; ks < 4; ++ks) {
            uint32_t ah[4] = { pA0[2 * ks], pA1[2 * ks], pA0[2 * ks + 1], pA1[2 * ks + 1] };
            uint32_t al[4] = { pL0[2 * ks], pL1[2 * ks], pL0[2 * ks + 1], pL1[2 * ks + 1] };
            #pragma unroll
            for (int ng = 0; ng < 4; ++ng) {
                const uint32_t off =
                    ((ks * 16 + (lane & 7) + (lane & 8)) * RSA + ng * 16 + ((lane >> 4) << 3)) * 2;
                uint32_t h0, h1, h2, h3, e0, e1, e2, e3;
                LDMX4T(h0, h1, h2, h3, Vhu + off);
                LDMX4T(e0, e1, e2, e3, Vlu + off);
                MMA16816_2(o[2 * ng],     ah, h0, h1);
                MMA16816_2(o[2 * ng],     al, h0, h1);
                MMA16816_2(o[2 * ng],     ah, e0, e1);
                MMA16816_2(o[2 * ng + 1], ah, h2, h3);
                MMA16816_2(o[2 * ng + 1], al, h2, h3);
                MMA16816_2(o[2 * ng + 1], ah, e2, e3);
            }
        }

        if (kt + 1 < nt) store_tile((kt + 1) & 1);
        __syncthreads();
    }

    // ---- normalize + write
    l0 += __shfl_xor_sync(0xffffffffu, l0, 1);
    l0 += __shfl_xor_sync(0xffffffffu, l0, 2);
    l1 += __shfl_xor_sync(0xffffffffu, l1, 1);
    l1 += __shfl_xor_sync(0xffffffffu, l1, 2);
    const float i0 = 1.f / l0, i1 = 1.f / l1;
    float* O0 = O + ((size_t)(b * SEQ + q_r0)) * DMODEL + h * DHEAD + 2 * (lane & 3);
    float* O1p = O + ((size_t)(b * SEQ + q_r1)) * DMODEL + h * DHEAD + 2 * (lane & 3);
    #pragma unroll
    for (int nf = 0; nf < 8; ++nf) {
        float2 v0 = {o[nf][0] * i0, o[nf][1] * i0};
        float2 v1 = {o[nf][2] * i1, o[nf][3] * i1};
        *reinterpret_cast<float2*>(O0  + nf * 8) = v0;
        *reinterpret_cast<float2*>(O1p + nf * 8) = v1;
    }
}

// ---------------------------------------------------------------------------
extern "C" void kernel_launch(void* const* d_in, const int* in_sizes, int n_in,
                              void* d_out, int out_size)
{
    const float* x     = (const float*)d_in[0];
    const float* basis = (const float*)d_in[1];
    const float* sq    = (const float*)d_in[2];
    const float* sk    = (const float*)d_in[3];
    const float* sv    = (const float*)d_in[4];
    const float* so    = (const float*)d_in[5];
    const float* bias  = (const float*)d_in[6];
    float*       out   = (float*)d_out;

    float *XB, *Qm, *Km, *Vm, *AO, *O1, *BT;
    cudaGetSymbolAddress((void**)&XB, g_XB);
    cudaGetSymbolAddress((void**)&Qm, g_Q);
    cudaGetSymbolAddress((void**)&Km, g_K);
    cudaGetSymbolAddress((void**)&Vm, g_V);
    cudaGetSymbolAddress((void**)&AO, g_AO);
    cudaGetSymbolAddress((void**)&O1, g_O1);
    cudaGetSymbolAddress((void**)&BT, g_basisT);

    cudaFuncSetAttribute(sgemm_mma<false>, cudaFuncAttributeMaxDynamicSharedMemorySize, SMEM_DYN);
    cudaFuncSetAttribute(sgemm_mma<true >, cudaFuncAttributeMaxDynamicSharedMemorySize, SMEM_DYN);
    cudaFuncSetAttribute(attn_mma, cudaFuncAttributeMaxDynamicSharedMemorySize, ASMEM);

    transpose_k<<<dim3(32, 32), dim3(32, 8)>>>(basis, BT);

    const dim3 gg(DMODEL / 128, MROWS / 128);
    sgemm_mma<false><<<gg, 256, SMEM_DYN>>>(x,  BT,    nullptr, XB);
    sgemm_mma<true ><<<gg, 256, SMEM_DYN>>>(XB, basis, sq, Qm);
    sgemm_mma<true ><<<gg, 256, SMEM_DYN>>>(XB, basis, sk, Km);
    sgemm_mma<true ><<<gg, 256, SMEM_DYN>>>(XB, basis, sv, Vm);

    attn_mma<<<dim3(SEQ / 128, NHEADS, BATCH), 256, ASMEM>>>(Qm, Km, Vm, bias, AO);

    sgemm_mma<false><<<gg, 256, SMEM_DYN>>>(AO, BT,    nullptr, O1);
    sgemm_mma<true ><<<gg, 256, SMEM_DYN>>>(O1, basis, so, out);
}

// round 5
// speedup vs baseline: 5.8945x; 1.1943x over previous
#include <cuda_runtime.h>
#include <cuda_bf16.h>
#include <cstdint>
#include <cstddef>

#define SEQ    2048
#define BATCH  2
#define DMODEL 1024
#define NHEADS 16
#define DHEAD  64
#define MROWS  (BATCH*SEQ)

// ---------------- scratch (device globals; allocation-free rule) ------------
__device__ __nv_bfloat16 g_Xh [(size_t)MROWS*DMODEL], g_Xl [(size_t)MROWS*DMODEL];
__device__ __nv_bfloat16 g_BTh[(size_t)DMODEL*DMODEL], g_BTl[(size_t)DMODEL*DMODEL];
__device__ __nv_bfloat16 g_Bmh[(size_t)DMODEL*DMODEL], g_Bml[(size_t)DMODEL*DMODEL];
__device__ __nv_bfloat16 g_XBqh[(size_t)MROWS*DMODEL], g_XBql[(size_t)MROWS*DMODEL];
__device__ __nv_bfloat16 g_XBkh[(size_t)MROWS*DMODEL], g_XBkl[(size_t)MROWS*DMODEL];
__device__ __nv_bfloat16 g_XBvh[(size_t)MROWS*DMODEL], g_XBvl[(size_t)MROWS*DMODEL];
__device__ __nv_bfloat16 g_AOh[(size_t)MROWS*DMODEL],  g_AOl[(size_t)MROWS*DMODEL];
__device__ __nv_bfloat16 g_O1h[(size_t)MROWS*DMODEL],  g_O1l[(size_t)MROWS*DMODEL];
__device__ float g_Q[(size_t)MROWS*DMODEL], g_K[(size_t)MROWS*DMODEL], g_V[(size_t)MROWS*DMODEL];

// ---------------------------------------------------------------------------
__device__ __forceinline__ uint32_t smem_u32(const void* p) {
    uint32_t a;
    asm("{ .reg .u64 t; cvta.to.shared.u64 t, %1; cvt.u32.u64 %0, t; }"
        : "=r"(a) : "l"(p));
    return a;
}

#define LDMX4(r0, r1, r2, r3, addr) \
    asm volatile("ldmatrix.sync.aligned.m8n8.x4.shared.b16 {%0,%1,%2,%3}, [%4];" \
                 : "=r"(r0), "=r"(r1), "=r"(r2), "=r"(r3) : "r"(addr))

#define LDMX4T(r0, r1, r2, r3, addr) \
    asm volatile("ldmatrix.sync.aligned.m8n8.x4.trans.shared.b16 {%0,%1,%2,%3}, [%4];" \
                 : "=r"(r0), "=r"(r1), "=r"(r2), "=r"(r3) : "r"(addr))

#define MMA16816(d, a, b) \
    asm volatile("mma.sync.aligned.m16n8k16.row.col.f32.bf16.bf16.f32 " \
                 "{%0,%1,%2,%3}, {%4,%5,%6,%7}, {%8,%9}, {%0,%1,%2,%3};" \
                 : "+f"((d)[0]), "+f"((d)[1]), "+f"((d)[2]), "+f"((d)[3]) \
                 : "r"((a)[0]), "r"((a)[1]), "r"((a)[2]), "r"((a)[3]), \
                   "r"((b)[0]), "r"((b)[1]))

#define MMA16816_2(d, a, b0r, b1r) \
    asm volatile("mma.sync.aligned.m16n8k16.row.col.f32.bf16.bf16.f32 " \
                 "{%0,%1,%2,%3}, {%4,%5,%6,%7}, {%8,%9}, {%0,%1,%2,%3};" \
                 : "+f"((d)[0]), "+f"((d)[1]), "+f"((d)[2]), "+f"((d)[3]) \
                 : "r"((a)[0]), "r"((a)[1]), "r"((a)[2]), "r"((a)[3]), \
                   "r"(b0r), "r"(b1r))

#define CPASYNC16(dst, src) \
    asm volatile("cp.async.cg.shared.global [%0], [%1], 16;" \
                 :: "r"(dst), "l"(src))
#define CPCOMMIT()  asm volatile("cp.async.commit_group;" ::: "memory")
#define CPWAIT(n)   asm volatile("cp.async.wait_group %0;" :: "n"(n) : "memory")

__device__ __forceinline__ uint32_t packbf(float a, float b) {
    __nv_bfloat16 x = __float2bfloat16(a), y = __float2bfloat16(b);
    return (uint32_t)__bfloat16_as_ushort(x) | ((uint32_t)__bfloat16_as_ushort(y) << 16);
}

// fp32x4 -> bf16 hi/lo split, two 8-byte stores
__device__ __forceinline__ void split_store(void* hp, void* lp, float4 v) {
    __nv_bfloat16 h0 = __float2bfloat16(v.x), h1 = __float2bfloat16(v.y);
    __nv_bfloat16 h2 = __float2bfloat16(v.z), h3 = __float2bfloat16(v.w);
    uint2 hu, lu;
    hu.x = (uint32_t)__bfloat16_as_ushort(h0) | ((uint32_t)__bfloat16_as_ushort(h1) << 16);
    hu.y = (uint32_t)__bfloat16_as_ushort(h2) | ((uint32_t)__bfloat16_as_ushort(h3) << 16);
    lu.x = packbf(v.x - __bfloat162float(h0), v.y - __bfloat162float(h1));
    lu.y = packbf(v.z - __bfloat162float(h2), v.w - __bfloat162float(h3));
    *reinterpret_cast<uint2*>(hp) = hu;
    *reinterpret_cast<uint2*>(lp) = lu;
}

// pair (a,b) -> hi u32 + lo u32 at elem offset off
__device__ __forceinline__ void store_pair(__nv_bfloat16* Ph, __nv_bfloat16* Pl,
                                           size_t off, float a, float b) {
    __nv_bfloat16 h0 = __float2bfloat16(a), h1 = __float2bfloat16(b);
    uint32_t hu = (uint32_t)__bfloat16_as_ushort(h0) | ((uint32_t)__bfloat16_as_ushort(h1) << 16);
    uint32_t lu = packbf(a - __bfloat162float(h0), b - __bfloat162float(h1));
    *reinterpret_cast<uint32_t*>(Ph + off) = hu;
    *reinterpret_cast<uint32_t*>(Pl + off) = lu;
}

// 2^y via FMA-pipe polynomial (no MUFU). y <= ~0; accuracy ~2.4e-6 rel.
__device__ __forceinline__ float exp2p(float y) {
    y = fmaxf(y, -120.f);
    float t = y + 12582912.f;
    int   n = (__float_as_int(t) & 0x7FFFFF) - 0x400000;
    float f = y - (t - 12582912.f);
    float p = 1.3333558146e-3f;
    p = fmaf(p, f, 9.6181291076e-3f);
    p = fmaf(p, f, 5.5504108664e-2f);
    p = fmaf(p, f, 2.4022650695e-1f);
    p = fmaf(p, f, 6.9314718056e-1f);
    p = fmaf(p, f, 1.0f);
    return __int_as_float(__float_as_int(p) + (n << 23));
}

// ---------------------------------------------------------------------------
// Pre-split helpers
// ---------------------------------------------------------------------------
__global__ void split_plain(const float4* __restrict__ in,
                            __nv_bfloat16* __restrict__ h, __nv_bfloat16* __restrict__ l) {
    size_t i = (size_t)blockIdx.x * 256 + threadIdx.x;
    float4 v = in[i];
    split_store(h + 4 * i, l + 4 * i, v);
}

__global__ void trans_split(const float* __restrict__ in,
                            __nv_bfloat16* __restrict__ oh, __nv_bfloat16* __restrict__ ol) {
    __shared__ float t[32][33];
    int bx = blockIdx.x * 32, by = blockIdx.y * 32;
    #pragma unroll
    for (int i = 0; i < 32; i += 8)
        t[threadIdx.y + i][threadIdx.x] = in[(size_t)(by + threadIdx.y + i) * DMODEL + bx + threadIdx.x];
    __syncthreads();
    #pragma unroll
    for (int i = 0; i < 32; i += 8) {
        float v = t[threadIdx.x][threadIdx.y + i];
        size_t o = (size_t)(bx + threadIdx.y + i) * DMODEL + by + threadIdx.x;
        __nv_bfloat16 hv = __float2bfloat16(v);
        oh[o] = hv;
        ol[o] = __float2bfloat16(v - __bfloat162float(hv));
    }
}

// ---------------------------------------------------------------------------
// bf16x3 mma.sync GEMM on pre-split operands.
// C[m,n] = sum_k A[m,k]*B[n,k], A=(Ah+Al), B=(Bh+Bl), both [.,1024] bf16.
// Tile 128x128, BK=32, 2-stage cp.async pipeline, 2 CTAs/SM.
// EPI: 0 = fp32 C; 1 = three scale-fused bf16 pairs; 2 = one scale-fused pair.
// ---------------------------------------------------------------------------
static constexpr int RS = 40;                       // row stride in bf16 elems
static constexpr int TILE_E  = 128 * RS;
static constexpr int STAGE_B = 4 * TILE_E * 2;      // 40960 bytes per stage
static constexpr int SMEM_DYN = 2 * STAGE_B;        // 81920

template<int EPI>
__global__ __launch_bounds__(256, 2)
void gemm_bf16x3(const __nv_bfloat16* __restrict__ Ah, const __nv_bfloat16* __restrict__ Al,
                 const __nv_bfloat16* __restrict__ Bh, const __nv_bfloat16* __restrict__ Bl,
                 float* __restrict__ C,
                 const float* __restrict__ s0, const float* __restrict__ s1,
                 const float* __restrict__ s2,
                 __nv_bfloat16* __restrict__ P0h, __nv_bfloat16* __restrict__ P0l,
                 __nv_bfloat16* __restrict__ P1h, __nv_bfloat16* __restrict__ P1l,
                 __nv_bfloat16* __restrict__ P2h, __nv_bfloat16* __restrict__ P2l)
{
    extern __shared__ char smem[];
    const int tid  = threadIdx.x;
    const int lane = tid & 31;
    const int wid  = tid >> 5;
    const int bm   = blockIdx.y * 128;
    const int bn   = blockIdx.x * 128;
    const int wm0  = (wid & 3) * 32;
    const int wn0  = (wid >> 2) * 64;
    const uint32_t sbase = smem_u32(smem);

    // cp.async geometry: per matrix-half, rows crow & crow+64, one 16B chunk
    const int crow = tid >> 2;            // 0..63
    const int cchk = (tid & 3) * 16;      // byte in 64B row segment

    const char* gA_h = (const char*)Ah + (size_t)(bm + crow) * 2048 + cchk;
    const char* gA_l = (const char*)Al + (size_t)(bm + crow) * 2048 + cchk;
    const char* gB_h = (const char*)Bh + (size_t)(bn + crow) * 2048 + cchk;
    const char* gB_l = (const char*)Bl + (size_t)(bn + crow) * 2048 + cchk;
    const uint32_t sm_r  = sbase + crow * 80u + cchk;

    auto issue_stage = [&](int c, int s) {
        const size_t k0b = (size_t)c * 64;
        const uint32_t st = sm_r + (uint32_t)s * STAGE_B;
        CPASYNC16(st,                      gA_h + k0b);
        CPASYNC16(st + 64u * 80u,          gA_h + k0b + (size_t)64 * 2048);
        CPASYNC16(st + 10240u,             gA_l + k0b);
        CPASYNC16(st + 10240u + 64u * 80u, gA_l + k0b + (size_t)64 * 2048);
        CPASYNC16(st + 20480u,             gB_h + k0b);
        CPASYNC16(st + 20480u + 64u * 80u, gB_h + k0b + (size_t)64 * 2048);
        CPASYNC16(st + 30720u,             gB_l + k0b);
        CPASYNC16(st + 30720u + 64u * 80u, gB_l + k0b + (size_t)64 * 2048);
        CPCOMMIT();
    };

    float acc[2][8][4];
    #pragma unroll
    for (int i = 0; i < 2; ++i)
        #pragma unroll
        for (int j = 0; j < 8; ++j)
            #pragma unroll
            for (int q = 0; q < 4; ++q) acc[i][j][q] = 0.f;

    auto compute = [&](int s) {
        const uint32_t st = sbase + s * STAGE_B;
        const uint32_t Ah_u = st;
        const uint32_t Al_u = st + 10240u;
        const uint32_t Bh_u = st + 20480u;
        const uint32_t Bl_u = st + 30720u;
        #pragma unroll
        for (int ks = 0; ks < 2; ++ks) {
            const int k0 = ks * 16;
            uint32_t ah[2][4], al[2][4];
            #pragma unroll
            for (int mt = 0; mt < 2; ++mt) {
                const uint32_t off =
                    ((wm0 + mt * 16 + (lane & 15)) * RS + k0 + ((lane >> 4) << 3)) * 2;
                LDMX4(ah[mt][0], ah[mt][1], ah[mt][2], ah[mt][3], Ah_u + off);
                LDMX4(al[mt][0], al[mt][1], al[mt][2], al[mt][3], Al_u + off);
            }
            #pragma unroll
            for (int bb = 0; bb < 4; ++bb) {
                const int n0 = wn0 + bb * 16;
                const uint32_t off =
                    ((n0 + (lane & 7) + ((lane >> 4) << 3)) * RS + k0 + (lane & 8)) * 2;
                uint32_t b0, b1, b2, b3, e0, e1, e2, e3;
                LDMX4(b0, b1, b2, b3, Bh_u + off);
                LDMX4(e0, e1, e2, e3, Bl_u + off);
                #pragma unroll
                for (int mt = 0; mt < 2; ++mt) {
                    MMA16816_2(acc[mt][2 * bb],     ah[mt], b0, b1);
                    MMA16816_2(acc[mt][2 * bb],     ah[mt], e0, e1);
                    MMA16816_2(acc[mt][2 * bb],     al[mt], b0, b1);
                    MMA16816_2(acc[mt][2 * bb + 1], ah[mt], b2, b3);
                    MMA16816_2(acc[mt][2 * bb + 1], ah[mt], e2, e3);
                    MMA16816_2(acc[mt][2 * bb + 1], al[mt], b2, b3);
                }
            }
        }
    };

    issue_stage(0, 0);
    issue_stage(1, 1);
    CPWAIT(1);
    __syncthreads();

    for (int c = 0; c < 32; ++c) {
        compute(c & 1);
        __syncthreads();
        if (c + 2 < 32) {
            issue_stage(c + 2, c & 1);
            CPWAIT(1);
        } else {
            CPWAIT(0);
        }
        __syncthreads();
    }

    // ---- epilogue
    #pragma unroll
    for (int mt = 0; mt < 2; ++mt) {
        const int m = bm + wm0 + mt * 16 + (lane >> 2);
        #pragma unroll
        for (int nf = 0; nf < 8; ++nf) {
            const int n = bn + wn0 + nf * 8 + (lane & 3) * 2;
            if (EPI == 0) {
                float2 v0 = {acc[mt][nf][0], acc[mt][nf][1]};
                float2 v1 = {acc[mt][nf][2], acc[mt][nf][3]};
                *reinterpret_cast<float2*>(C + (size_t)m * DMODEL + n) = v0;
                *reinterpret_cast<float2*>(C + (size_t)(m + 8) * DMODEL + n) = v1;
            } else {
                const size_t o0 = (size_t)m * DMODEL + n;
                const size_t o1 = (size_t)(m + 8) * DMODEL + n;
                float2 sc0 = *reinterpret_cast<const float2*>(s0 + n);
                store_pair(P0h, P0l, o0, acc[mt][nf][0] * sc0.x, acc[mt][nf][1] * sc0.y);
                store_pair(P0h, P0l, o1, acc[mt][nf][2] * sc0.x, acc[mt][nf][3] * sc0.y);
                if (EPI == 1) {
                    float2 sc1 = *reinterpret_cast<const float2*>(s1 + n);
                    float2 sc2 = *reinterpret_cast<const float2*>(s2 + n);
                    store_pair(P1h, P1l, o0, acc[mt][nf][0] * sc1.x, acc[mt][nf][1] * sc1.y);
                    store_pair(P1h, P1l, o1, acc[mt][nf][2] * sc1.x, acc[mt][nf][3] * sc1.y);
                    store_pair(P2h, P2l, o0, acc[mt][nf][0] * sc2.x, acc[mt][nf][1] * sc2.y);
                    store_pair(P2h, P2l, o1, acc[mt][nf][2] * sc2.x, acc[mt][nf][3] * sc2.y);
                }
            }
        }
    }
}

// ---------------------------------------------------------------------------
// mma.sync flash attention (round-4), epilogue writes pre-split AO pairs.
// ---------------------------------------------------------------------------
static constexpr int RSA     = 72;
static constexpr int AT_MAT  = 64 * RSA;
static constexpr int AT_STG  = 4 * AT_MAT;
static constexpr int ASMEM   = 2 * AT_STG * 2;

__global__ __launch_bounds__(256, 1)
void attn_mma(const float* __restrict__ Q, const float* __restrict__ K,
              const float* __restrict__ V, const float* __restrict__ bias,
              __nv_bfloat16* __restrict__ AOh, __nv_bfloat16* __restrict__ AOl)
{
    extern __shared__ __nv_bfloat16 asmem[];
    const int tid  = threadIdx.x;
    const int lane = tid & 31;
    const int w    = tid >> 5;
    const int qt   = (int)gridDim.x - 1 - (int)blockIdx.x;
    const int h    = blockIdx.y;
    const int b    = blockIdx.z;
    const int q0   = qt * 128;
    const uint32_t sbase = smem_u32(asmem);

    {
        const float* Qb = Q + ((size_t)(b * SEQ + q0)) * DMODEL + h * DHEAD;
        #pragma unroll
        for (int i = 0; i < 8; ++i) {
            int idx = tid + i * 256;
            int row = idx >> 4, c4 = (idx & 15) * 4;
            float4 v = *reinterpret_cast<const float4*>(Qb + (size_t)row * DMODEL + c4);
            int off = row * RSA + c4;
            split_store(asmem + AT_STG + off, asmem + AT_STG + 128 * RSA + off, v);
        }
    }
    __syncthreads();
    uint32_t qh[4][4], ql[4][4];
    #pragma unroll
    for (int ks = 0; ks < 4; ++ks) {
        const uint32_t off = ((w * 16 + (lane & 15)) * RSA + ks * 16 + ((lane >> 4) << 3)) * 2;
        LDMX4(qh[ks][0], qh[ks][1], qh[ks][2], qh[ks][3], sbase + AT_STG * 2 + off);
        LDMX4(ql[ks][0], ql[ks][1], ql[ks][2], ql[ks][3], sbase + (AT_STG + 128 * RSA) * 2 + off);
    }
    __syncthreads();

    float m0 = -1e30f, m1 = -1e30f, l0 = 0.f, l1 = 0.f;
    float o[8][4];
    #pragma unroll
    for (int j = 0; j < 8; ++j)
        #pragma unroll
        for (int q = 0; q < 4; ++q) o[j][q] = 0.f;

    const int q_r0 = q0 + w * 16 + (lane >> 2);
    const int q_r1 = q_r0 + 8;
    const float* bph = bias + (size_t)h * SEQ * SEQ;
    const int nt = 2 * qt + 2;

    const int grow = tid >> 4;
    const int gc4  = (tid & 15) * 4;
    float4 kreg[4], vreg[4];

    auto load_tile = [&](int kt) {
        const int k0 = kt * 64;
        const float* Kb = K + ((size_t)(b * SEQ + k0 + grow)) * DMODEL + h * DHEAD + gc4;
        const float* Vb = V + ((size_t)(b * SEQ + k0 + grow)) * DMODEL + h * DHEAD + gc4;
        #pragma unroll
        for (int i = 0; i < 4; ++i) kreg[i] = *reinterpret_cast<const float4*>(Kb + (size_t)i * 16 * DMODEL);
        #pragma unroll
        for (int i = 0; i < 4; ++i) vreg[i] = *reinterpret_cast<const float4*>(Vb + (size_t)i * 16 * DMODEL);
    };
    auto store_tile = [&](int s) {
        __nv_bfloat16* st = asmem + s * AT_STG;
        #pragma unroll
        for (int i = 0; i < 4; ++i) {
            const int off = (grow + i * 16) * RSA + gc4;
            split_store(st + off,              st + AT_MAT + off,     kreg[i]);
            split_store(st + 2 * AT_MAT + off, st + 3 * AT_MAT + off, vreg[i]);
        }
    };

    load_tile(0);
    store_tile(0);
    __syncthreads();

    for (int kt = 0; kt < nt; ++kt) {
        const int s  = kt & 1;
        const int k0 = kt * 64;
        if (kt + 1 < nt) load_tile(kt + 1);

        const uint32_t Khu = sbase + s * AT_STG * 2;
        const uint32_t Klu = Khu + AT_MAT * 2;
        const uint32_t Vhu = Khu + 2 * AT_MAT * 2;
        const uint32_t Vlu = Khu + 3 * AT_MAT * 2;

        float sacc[8][4];
        #pragma unroll
        for (int j = 0; j < 8; ++j)
            #pragma unroll
            for (int q = 0; q < 4; ++q) sacc[j][q] = 0.f;
        #pragma unroll
        for (int ks = 0; ks < 4; ++ks) {
            #pragma unroll
            for (int bb = 0; bb < 4; ++bb) {
                const uint32_t off =
                    ((bb * 16 + (lane & 7) + ((lane >> 4) << 3)) * RSA + ks * 16 + (lane & 8)) * 2;
                uint32_t h0, h1, h2, h3, e0, e1, e2, e3;
                LDMX4(h0, h1, h2, h3, Khu + off);
                LDMX4(e0, e1, e2, e3, Klu + off);
                MMA16816_2(sacc[2 * bb],     qh[ks], h0, h1);
                MMA16816_2(sacc[2 * bb],     qh[ks], e0, e1);
                MMA16816_2(sacc[2 * bb],     ql[ks], h0, h1);
                MMA16816_2(sacc[2 * bb + 1], qh[ks], h2, h3);
                MMA16816_2(sacc[2 * bb + 1], qh[ks], e2, e3);
                MMA16816_2(sacc[2 * bb + 1], ql[ks], h2, h3);
            }
        }

        const bool mask = (kt >= 2 * qt);
        const float* r0p = bph + (size_t)q_r0 * SEQ + k0 + 2 * (lane & 3);
        const float* r1p = bph + (size_t)q_r1 * SEQ + k0 + 2 * (lane & 3);
        #pragma unroll
        for (int nf = 0; nf < 8; ++nf) {
            float2 b0 = *reinterpret_cast<const float2*>(r0p + nf * 8);
            float2 b1 = *reinterpret_cast<const float2*>(r1p + nf * 8);
            float v0 = fmaf(sacc[nf][0], 0.18033688f, b0.x * 1.4426950f);
            float v1 = fmaf(sacc[nf][1], 0.18033688f, b0.y * 1.4426950f);
            float v2 = fmaf(sacc[nf][2], 0.18033688f, b1.x * 1.4426950f);
            float v3 = fmaf(sacc[nf][3], 0.18033688f, b1.y * 1.4426950f);
            if (mask) {
                const int kc = k0 + nf * 8 + 2 * (lane & 3);
                if (kc     > q_r0) v0 = -1e30f;
                if (kc + 1 > q_r0) v1 = -1e30f;
                if (kc     > q_r1) v2 = -1e30f;
                if (kc + 1 > q_r1) v3 = -1e30f;
            }
            sacc[nf][0] = v0; sacc[nf][1] = v1; sacc[nf][2] = v2; sacc[nf][3] = v3;
        }

        float m0n = m0, m1n = m1;
        #pragma unroll
        for (int nf = 0; nf < 8; ++nf) {
            m0n = fmaxf(m0n, fmaxf(sacc[nf][0], sacc[nf][1]));
            m1n = fmaxf(m1n, fmaxf(sacc[nf][2], sacc[nf][3]));
        }
        m0n = fmaxf(m0n, __shfl_xor_sync(0xffffffffu, m0n, 1));
        m0n = fmaxf(m0n, __shfl_xor_sync(0xffffffffu, m0n, 2));
        m1n = fmaxf(m1n, __shfl_xor_sync(0xffffffffu, m1n, 1));
        m1n = fmaxf(m1n, __shfl_xor_sync(0xffffffffu, m1n, 2));
        const float c0 = exp2p(m0 - m0n), c1 = exp2p(m1 - m1n);
        m0 = m0n; m1 = m1n;
        l0 *= c0;  l1 *= c1;
        #pragma unroll
        for (int nf = 0; nf < 8; ++nf) {
            o[nf][0] *= c0; o[nf][1] *= c0;
            o[nf][2] *= c1; o[nf][3] *= c1;
        }

        uint32_t pA0[8], pA1[8], pL0[8], pL1[8];
        #pragma unroll
        for (int nf = 0; nf < 8; ++nf) {
            float p0 = exp2p(sacc[nf][0] - m0);
            float p1 = exp2p(sacc[nf][1] - m0);
            float p2 = exp2p(sacc[nf][2] - m1);
            float p3 = exp2p(sacc[nf][3] - m1);
            l0 += p0 + p1; l1 += p2 + p3;
            __nv_bfloat16 h0 = __float2bfloat16(p0), h1 = __float2bfloat16(p1);
            __nv_bfloat16 h2 = __float2bfloat16(p2), h3 = __float2bfloat16(p3);
            pA0[nf] = (uint32_t)__bfloat16_as_ushort(h0) | ((uint32_t)__bfloat16_as_ushort(h1) << 16);
            pA1[nf] = (uint32_t)__bfloat16_as_ushort(h2) | ((uint32_t)__bfloat16_as_ushort(h3) << 16);
            pL0[nf] = packbf(p0 - __bfloat162float(h0), p1 - __bfloat162float(h1));
            pL1[nf] = packbf(p2 - __bfloat162float(h2), p3 - __bfloat162float(h3));
        }

        #pragma unroll
        for (int ks = 0; ks < 4; ++ks) {
            uint32_t ah[4] = { pA0[2 * ks], pA1[2 * ks], pA0[2 * ks + 1], pA1[2 * ks + 1] };
            uint32_t al[4] = { pL0[2 * ks], pL1[2 * ks], pL0[2 * ks + 1], pL1[2 * ks + 1] };
            #pragma unroll
            for (int ng = 0; ng < 4; ++ng) {
                const uint32_t off =
                    ((ks * 16 + (lane & 7) + (lane & 8)) * RSA + ng * 16 + ((lane >> 4) << 3)) * 2;
                uint32_t h0, h1, h2, h3, e0, e1, e2, e3;
                LDMX4T(h0, h1, h2, h3, Vhu + off);
                LDMX4T(e0, e1, e2, e3, Vlu + off);
                MMA16816_2(o[2 * ng],     ah, h0, h1);
                MMA16816_2(o[2 * ng],     al, h0, h1);
                MMA16816_2(o[2 * ng],     ah, e0, e1);
                MMA16816_2(o[2 * ng + 1], ah, h2, h3);
                MMA16816_2(o[2 * ng + 1], al, h2, h3);
                MMA16816_2(o[2 * ng + 1], ah, e2, e3);
            }
        }

        if (kt + 1 < nt) store_tile((kt + 1) & 1);
        __syncthreads();
    }

    l0 += __shfl_xor_sync(0xffffffffu, l0, 1);
    l0 += __shfl_xor_sync(0xffffffffu, l0, 2);
    l1 += __shfl_xor_sync(0xffffffffu, l1, 1);
    l1 += __shfl_xor_sync(0xffffffffu, l1, 2);
    const float i0 = 1.f / l0, i1 = 1.f / l1;
    const size_t r0off = (size_t)(b * SEQ + q_r0) * DMODEL + h * DHEAD + 2 * (lane & 3);
    const size_t r1off = (size_t)(b * SEQ + q_r1) * DMODEL + h * DHEAD + 2 * (lane & 3);
    #pragma unroll
    for (int nf = 0; nf < 8; ++nf) {
        store_pair(AOh, AOl, r0off + nf * 8, o[nf][0] * i0, o[nf][1] * i0);
        store_pair(AOh, AOl, r1off + nf * 8, o[nf][2] * i1, o[nf][3] * i1);
    }
}

// ---------------------------------------------------------------------------
extern "C" void kernel_launch(void* const* d_in, const int* in_sizes, int n_in,
                              void* d_out, int out_size)
{
    const float* x     = (const float*)d_in[0];
    const float* basis = (const float*)d_in[1];
    const float* sq    = (const float*)d_in[2];
    const float* sk    = (const float*)d_in[3];
    const float* sv    = (const float*)d_in[4];
    const float* so    = (const float*)d_in[5];
    const float* bias  = (const float*)d_in[6];
    float*       out   = (float*)d_out;

    __nv_bfloat16 *Xh, *Xl, *BTh, *BTl, *Bmh, *Bml;
    __nv_bfloat16 *XBqh, *XBql, *XBkh, *XBkl, *XBvh, *XBvl;
    __nv_bfloat16 *AOh, *AOl, *O1h, *O1l;
    float *Qm, *Km, *Vm;
    cudaGetSymbolAddress((void**)&Xh,  g_Xh);  cudaGetSymbolAddress((void**)&Xl,  g_Xl);
    cudaGetSymbolAddress((void**)&BTh, g_BTh); cudaGetSymbolAddress((void**)&BTl, g_BTl);
    cudaGetSymbolAddress((void**)&Bmh, g_Bmh); cudaGetSymbolAddress((void**)&Bml, g_Bml);
    cudaGetSymbolAddress((void**)&XBqh, g_XBqh); cudaGetSymbolAddress((void**)&XBql, g_XBql);
    cudaGetSymbolAddress((void**)&XBkh, g_XBkh); cudaGetSymbolAddress((void**)&XBkl, g_XBkl);
    cudaGetSymbolAddress((void**)&XBvh, g_XBvh); cudaGetSymbolAddress((void**)&XBvl, g_XBvl);
    cudaGetSymbolAddress((void**)&AOh, g_AOh); cudaGetSymbolAddress((void**)&AOl, g_AOl);
    cudaGetSymbolAddress((void**)&O1h, g_O1h); cudaGetSymbolAddress((void**)&O1l, g_O1l);
    cudaGetSymbolAddress((void**)&Qm, g_Q);
    cudaGetSymbolAddress((void**)&Km, g_K);
    cudaGetSymbolAddress((void**)&Vm, g_V);

    cudaFuncSetAttribute(gemm_bf16x3<0>, cudaFuncAttributeMaxDynamicSharedMemorySize, SMEM_DYN);
    cudaFuncSetAttribute(gemm_bf16x3<1>, cudaFuncAttributeMaxDynamicSharedMemorySize, SMEM_DYN);
    cudaFuncSetAttribute(gemm_bf16x3<2>, cudaFuncAttributeMaxDynamicSharedMemorySize, SMEM_DYN);
    cudaFuncSetAttribute(attn_mma, cudaFuncAttributeMaxDynamicSharedMemorySize, ASMEM);

    // pre-split inputs
    split_plain<<<MROWS * DMODEL / 1024, 256>>>((const float4*)x, Xh, Xl);
    split_plain<<<DMODEL * DMODEL / 1024, 256>>>((const float4*)basis, Bmh, Bml);
    trans_split<<<dim3(32, 32), dim3(32, 8)>>>(basis, BTh, BTl);

    const dim3 gg(DMODEL / 128, MROWS / 128);
    // G1: XB = X @ basis, epilogue emits scale-fused pairs for q/k/v
    gemm_bf16x3<1><<<gg, 256, SMEM_DYN>>>(Xh, Xl, BTh, BTl, nullptr,
                                          sq, sk, sv,
                                          XBqh, XBql, XBkh, XBkl, XBvh, XBvl);
    // G2-4: Q/K/V fp32
    gemm_bf16x3<0><<<gg, 256, SMEM_DYN>>>(XBqh, XBql, Bmh, Bml, Qm,
                                          nullptr, nullptr, nullptr,
                                          nullptr, nullptr, nullptr, nullptr, nullptr, nullptr);
    gemm_bf16x3<0><<<gg, 256, SMEM_DYN>>>(XBkh, XBkl, Bmh, Bml, Km,
                                          nullptr, nullptr, nullptr,
                                          nullptr, nullptr, nullptr, nullptr, nullptr, nullptr);
    gemm_bf16x3<0><<<gg, 256, SMEM_DYN>>>(XBvh, XBvl, Bmh, Bml, Vm,
                                          nullptr, nullptr, nullptr,
                                          nullptr, nullptr, nullptr, nullptr, nullptr, nullptr);

    attn_mma<<<dim3(SEQ / 128, NHEADS, BATCH), 256, ASMEM>>>(Qm, Km, Vm, bias, AOh, AOl);

    // G5: O1 = AO @ basis, epilogue emits so-fused pair
    gemm_bf16x3<2><<<gg, 256, SMEM_DYN>>>(AOh, AOl, BTh, BTl, nullptr,
                                          so, nullptr, nullptr,
                                          O1h, O1l, nullptr, nullptr, nullptr, nullptr);
    // G6: out = O1s @ basis^T, fp32
    gemm_bf16x3<0><<<gg, 256, SMEM_DYN>>>(O1h, O1l, Bmh, Bml, out,
                                          nullptr, nullptr, nullptr,
                                          nullptr, nullptr, nullptr, nullptr, nullptr, nullptr);
}

// round 6
// speedup vs baseline: 6.4812x; 1.0995x over previous
#include <cuda_runtime.h>
#include <cuda_bf16.h>
#include <cstdint>
#include <cstddef>

#define SEQ    2048
#define BATCH  2
#define DMODEL 1024
#define NHEADS 16
#define DHEAD  64
#define MROWS  (BATCH*SEQ)

// ---------------- scratch (device globals; allocation-free rule) ------------
__device__ __nv_bfloat16 g_Xh [(size_t)MROWS*DMODEL], g_Xl [(size_t)MROWS*DMODEL];
__device__ __nv_bfloat16 g_BTh[(size_t)DMODEL*DMODEL], g_BTl[(size_t)DMODEL*DMODEL];
__device__ __nv_bfloat16 g_Bmh[(size_t)DMODEL*DMODEL], g_Bml[(size_t)DMODEL*DMODEL];
__device__ __nv_bfloat16 g_XBqh[(size_t)MROWS*DMODEL], g_XBql[(size_t)MROWS*DMODEL];
__device__ __nv_bfloat16 g_XBkh[(size_t)MROWS*DMODEL], g_XBkl[(size_t)MROWS*DMODEL];
__device__ __nv_bfloat16 g_XBvh[(size_t)MROWS*DMODEL], g_XBvl[(size_t)MROWS*DMODEL];
__device__ __nv_bfloat16 g_AOh[(size_t)MROWS*DMODEL],  g_AOl[(size_t)MROWS*DMODEL];
__device__ __nv_bfloat16 g_O1h[(size_t)MROWS*DMODEL],  g_O1l[(size_t)MROWS*DMODEL];
__device__ float g_Q[(size_t)MROWS*DMODEL], g_K[(size_t)MROWS*DMODEL], g_V[(size_t)MROWS*DMODEL];

// ---------------------------------------------------------------------------
__device__ __forceinline__ uint32_t smem_u32(const void* p) {
    uint32_t a;
    asm("{ .reg .u64 t; cvta.to.shared.u64 t, %1; cvt.u32.u64 %0, t; }"
        : "=r"(a) : "l"(p));
    return a;
}

#define LDMX4(r0, r1, r2, r3, addr) \
    asm volatile("ldmatrix.sync.aligned.m8n8.x4.shared.b16 {%0,%1,%2,%3}, [%4];" \
                 : "=r"(r0), "=r"(r1), "=r"(r2), "=r"(r3) : "r"(addr))

#define LDMX4T(r0, r1, r2, r3, addr) \
    asm volatile("ldmatrix.sync.aligned.m8n8.x4.trans.shared.b16 {%0,%1,%2,%3}, [%4];" \
                 : "=r"(r0), "=r"(r1), "=r"(r2), "=r"(r3) : "r"(addr))

#define MMA16816_2(d, a, b0r, b1r) \
    asm volatile("mma.sync.aligned.m16n8k16.row.col.f32.bf16.bf16.f32 " \
                 "{%0,%1,%2,%3}, {%4,%5,%6,%7}, {%8,%9}, {%0,%1,%2,%3};" \
                 : "+f"((d)[0]), "+f"((d)[1]), "+f"((d)[2]), "+f"((d)[3]) \
                 : "r"((a)[0]), "r"((a)[1]), "r"((a)[2]), "r"((a)[3]), \
                   "r"(b0r), "r"(b1r))

#define CPASYNC16(dst, src) \
    asm volatile("cp.async.cg.shared.global [%0], [%1], 16;" \
                 :: "r"(dst), "l"(src))
#define CPCOMMIT()  asm volatile("cp.async.commit_group;" ::: "memory")
#define CPWAIT(n)   asm volatile("cp.async.wait_group %0;" :: "n"(n) : "memory")

// XOR swizzle: 16B chunk index ^= row-pair (64B rows, conflict-free ldmatrix)
__device__ __forceinline__ uint32_t swz(uint32_t o) {
    return o ^ (((o >> 7) & 3u) << 4);
}

__device__ __forceinline__ uint32_t packbf(float a, float b) {
    __nv_bfloat16 x = __float2bfloat16(a), y = __float2bfloat16(b);
    return (uint32_t)__bfloat16_as_ushort(x) | ((uint32_t)__bfloat16_as_ushort(y) << 16);
}

// fp32x4 -> bf16 hi/lo split, two 8-byte stores
__device__ __forceinline__ void split_store(void* hp, void* lp, float4 v) {
    __nv_bfloat16 h0 = __float2bfloat16(v.x), h1 = __float2bfloat16(v.y);
    __nv_bfloat16 h2 = __float2bfloat16(v.z), h3 = __float2bfloat16(v.w);
    uint2 hu, lu;
    hu.x = (uint32_t)__bfloat16_as_ushort(h0) | ((uint32_t)__bfloat16_as_ushort(h1) << 16);
    hu.y = (uint32_t)__bfloat16_as_ushort(h2) | ((uint32_t)__bfloat16_as_ushort(h3) << 16);
    lu.x = packbf(v.x - __bfloat162float(h0), v.y - __bfloat162float(h1));
    lu.y = packbf(v.z - __bfloat162float(h2), v.w - __bfloat162float(h3));
    *reinterpret_cast<uint2*>(hp) = hu;
    *reinterpret_cast<uint2*>(lp) = lu;
}

__device__ __forceinline__ void store_pair(__nv_bfloat16* Ph, __nv_bfloat16* Pl,
                                           size_t off, float a, float b) {
    __nv_bfloat16 h0 = __float2bfloat16(a), h1 = __float2bfloat16(b);
    uint32_t hu = (uint32_t)__bfloat16_as_ushort(h0) | ((uint32_t)__bfloat16_as_ushort(h1) << 16);
    uint32_t lu = packbf(a - __bfloat162float(h0), b - __bfloat162float(h1));
    *reinterpret_cast<uint32_t*>(Ph + off) = hu;
    *reinterpret_cast<uint32_t*>(Pl + off) = lu;
}

// 2^y via FMA-pipe polynomial (no MUFU)
__device__ __forceinline__ float exp2p(float y) {
    y = fmaxf(y, -120.f);
    float t = y + 12582912.f;
    int   n = (__float_as_int(t) & 0x7FFFFF) - 0x400000;
    float f = y - (t - 12582912.f);
    float p = 1.3333558146e-3f;
    p = fmaf(p, f, 9.6181291076e-3f);
    p = fmaf(p, f, 5.5504108664e-2f);
    p = fmaf(p, f, 2.4022650695e-1f);
    p = fmaf(p, f, 6.9314718056e-1f);
    p = fmaf(p, f, 1.0f);
    return __int_as_float(__float_as_int(p) + (n << 23));
}

// ---------------------------------------------------------------------------
// Pre-split helpers
// ---------------------------------------------------------------------------
__global__ void split_plain(const float4* __restrict__ in,
                            __nv_bfloat16* __restrict__ h, __nv_bfloat16* __restrict__ l) {
    size_t i = (size_t)blockIdx.x * 256 + threadIdx.x;
    float4 v = in[i];
    split_store(h + 4 * i, l + 4 * i, v);
}

__global__ void trans_split(const float* __restrict__ in,
                            __nv_bfloat16* __restrict__ oh, __nv_bfloat16* __restrict__ ol) {
    __shared__ float t[32][33];
    int bx = blockIdx.x * 32, by = blockIdx.y * 32;
    #pragma unroll
    for (int i = 0; i < 32; i += 8)
        t[threadIdx.y + i][threadIdx.x] = in[(size_t)(by + threadIdx.y + i) * DMODEL + bx + threadIdx.x];
    __syncthreads();
    #pragma unroll
    for (int i = 0; i < 32; i += 8) {
        float v = t[threadIdx.x][threadIdx.y + i];
        size_t o = (size_t)(bx + threadIdx.y + i) * DMODEL + by + threadIdx.x;
        __nv_bfloat16 hv = __float2bfloat16(v);
        oh[o] = hv;
        ol[o] = __float2bfloat16(v - __bfloat162float(hv));
    }
}

// ---------------------------------------------------------------------------
// bf16x3 mma.sync GEMM, 3-stage cp.async pipeline, XOR-swizzled 64B rows.
// Tile 128x128, BK=32. Stage = Ah|Al|Bh|Bl @ 8KB each = 32KB; 3 stages.
// One __syncthreads per chunk; copies issued before compute.
// ---------------------------------------------------------------------------
static constexpr int STAGE_B  = 32768;
static constexpr int SMEM_DYN = 3 * STAGE_B;     // 98304; 2 CTAs/SM = 192KB

template<int EPI>
__global__ __launch_bounds__(256, 2)
void gemm_bf16x3(const __nv_bfloat16* __restrict__ Ah, const __nv_bfloat16* __restrict__ Al,
                 const __nv_bfloat16* __restrict__ Bh, const __nv_bfloat16* __restrict__ Bl,
                 float* __restrict__ C,
                 const float* __restrict__ s0, const float* __restrict__ s1,
                 const float* __restrict__ s2,
                 __nv_bfloat16* __restrict__ P0h, __nv_bfloat16* __restrict__ P0l,
                 __nv_bfloat16* __restrict__ P1h, __nv_bfloat16* __restrict__ P1l,
                 __nv_bfloat16* __restrict__ P2h, __nv_bfloat16* __restrict__ P2l)
{
    extern __shared__ char smem[];
    const int tid  = threadIdx.x;
    const int lane = tid & 31;
    const int wid  = tid >> 5;
    const int bm   = blockIdx.y * 128;
    const int bn   = blockIdx.x * 128;
    const int wm0  = (wid & 3) * 32;
    const int wn0  = (wid >> 2) * 64;
    const uint32_t sbase = smem_u32(smem);

    // cp.async geometry: rows crow & crow+64, one swizzled 16B chunk each
    const int crow = tid >> 2;            // 0..63
    const int cchk = (tid & 3) * 16;      // byte within 64B row

    const char* gA_h = (const char*)Ah + (size_t)(bm + crow) * 2048 + cchk;
    const char* gA_l = (const char*)Al + (size_t)(bm + crow) * 2048 + cchk;
    const char* gB_h = (const char*)Bh + (size_t)(bn + crow) * 2048 + cchk;
    const char* gB_l = (const char*)Bl + (size_t)(bn + crow) * 2048 + cchk;

    const uint32_t so1 = swz((uint32_t)(crow * 64 + cchk));
    const uint32_t so2 = swz((uint32_t)(crow * 64 + cchk) + 4096u);

    auto issue_stage = [&](int c, int s) {
        const size_t k0b = (size_t)c * 64;
        const uint32_t st = sbase + (uint32_t)s * STAGE_B;
        CPASYNC16(st + so1,          gA_h + k0b);
        CPASYNC16(st + so2,          gA_h + k0b + (size_t)64 * 2048);
        CPASYNC16(st + 8192u  + so1, gA_l + k0b);
        CPASYNC16(st + 8192u  + so2, gA_l + k0b + (size_t)64 * 2048);
        CPASYNC16(st + 16384u + so1, gB_h + k0b);
        CPASYNC16(st + 16384u + so2, gB_h + k0b + (size_t)64 * 2048);
        CPASYNC16(st + 24576u + so1, gB_l + k0b);
        CPASYNC16(st + 24576u + so2, gB_l + k0b + (size_t)64 * 2048);
        CPCOMMIT();
    };

    float acc[2][8][4];
    #pragma unroll
    for (int i = 0; i < 2; ++i)
        #pragma unroll
        for (int j = 0; j < 8; ++j)
            #pragma unroll
            for (int q = 0; q < 4; ++q) acc[i][j][q] = 0.f;

    // pre-swizzled frag offsets (k-step 0); k-step 1 adds 32B pre-swizzle
    uint32_t aoff[2], boff[4];
    #pragma unroll
    for (int mt = 0; mt < 2; ++mt)
        aoff[mt] = (uint32_t)((wm0 + mt * 16 + (lane & 15)) * 64 + ((lane >> 4) << 4));
    #pragma unroll
    for (int bb = 0; bb < 4; ++bb)
        boff[bb] = (uint32_t)((wn0 + bb * 16 + (lane & 7) + ((lane >> 4) << 3)) * 64 + ((lane & 8) << 1));

    auto compute = [&](int s) {
        const uint32_t st = sbase + (uint32_t)s * STAGE_B;
        #pragma unroll
        for (int ks = 0; ks < 2; ++ks) {
            const uint32_t kb = ks * 32u;
            uint32_t ah[2][4], al[2][4];
            #pragma unroll
            for (int mt = 0; mt < 2; ++mt) {
                const uint32_t off = swz(aoff[mt] + kb);
                LDMX4(ah[mt][0], ah[mt][1], ah[mt][2], ah[mt][3], st + off);
                LDMX4(al[mt][0], al[mt][1], al[mt][2], al[mt][3], st + 8192u + off);
            }
            #pragma unroll
            for (int bb = 0; bb < 4; ++bb) {
                const uint32_t off = swz(boff[bb] + kb);
                uint32_t b0, b1, b2, b3, e0, e1, e2, e3;
                LDMX4(b0, b1, b2, b3, st + 16384u + off);
                LDMX4(e0, e1, e2, e3, st + 24576u + off);
                #pragma unroll
                for (int mt = 0; mt < 2; ++mt) {
                    MMA16816_2(acc[mt][2 * bb],     ah[mt], b0, b1);
                    MMA16816_2(acc[mt][2 * bb],     ah[mt], e0, e1);
                    MMA16816_2(acc[mt][2 * bb],     al[mt], b0, b1);
                    MMA16816_2(acc[mt][2 * bb + 1], ah[mt], b2, b3);
                    MMA16816_2(acc[mt][2 * bb + 1], ah[mt], e2, e3);
                    MMA16816_2(acc[mt][2 * bb + 1], al[mt], b2, b3);
                }
            }
        }
    };

    issue_stage(0, 0);
    issue_stage(1, 1);

    for (int c = 0; c < 32; ++c) {
        if (c < 31) { CPWAIT(1); } else { CPWAIT(0); }
        __syncthreads();
        if (c + 2 < 32) issue_stage(c + 2, (c + 2) % 3);
        compute(c % 3);
    }

    // ---- epilogue
    #pragma unroll
    for (int mt = 0; mt < 2; ++mt) {
        const int m = bm + wm0 + mt * 16 + (lane >> 2);
        #pragma unroll
        for (int nf = 0; nf < 8; ++nf) {
            const int n = bn + wn0 + nf * 8 + (lane & 3) * 2;
            if (EPI == 0) {
                float2 v0 = {acc[mt][nf][0], acc[mt][nf][1]};
                float2 v1 = {acc[mt][nf][2], acc[mt][nf][3]};
                *reinterpret_cast<float2*>(C + (size_t)m * DMODEL + n) = v0;
                *reinterpret_cast<float2*>(C + (size_t)(m + 8) * DMODEL + n) = v1;
            } else {
                const size_t o0 = (size_t)m * DMODEL + n;
                const size_t o1 = (size_t)(m + 8) * DMODEL + n;
                float2 sc0 = *reinterpret_cast<const float2*>(s0 + n);
                store_pair(P0h, P0l, o0, acc[mt][nf][0] * sc0.x, acc[mt][nf][1] * sc0.y);
                store_pair(P0h, P0l, o1, acc[mt][nf][2] * sc0.x, acc[mt][nf][3] * sc0.y);
                if (EPI == 1) {
                    float2 sc1 = *reinterpret_cast<const float2*>(s1 + n);
                    float2 sc2 = *reinterpret_cast<const float2*>(s2 + n);
                    store_pair(P1h, P1l, o0, acc[mt][nf][0] * sc1.x, acc[mt][nf][1] * sc1.y);
                    store_pair(P1h, P1l, o1, acc[mt][nf][2] * sc1.x, acc[mt][nf][3] * sc1.y);
                    store_pair(P2h, P2l, o0, acc[mt][nf][0] * sc2.x, acc[mt][nf][1] * sc2.y);
                    store_pair(P2h, P2l, o1, acc[mt][nf][2] * sc2.x, acc[mt][nf][3] * sc2.y);
                }
            }
        }
    }
}

// ---------------------------------------------------------------------------
// mma.sync flash attention (unchanged from round 5)
// ---------------------------------------------------------------------------
static constexpr int RSA     = 72;
static constexpr int AT_MAT  = 64 * RSA;
static constexpr int AT_STG  = 4 * AT_MAT;
static constexpr int ASMEM   = 2 * AT_STG * 2;

__global__ __launch_bounds__(256, 1)
void attn_mma(const float* __restrict__ Q, const float* __restrict__ K,
              const float* __restrict__ V, const float* __restrict__ bias,
              __nv_bfloat16* __restrict__ AOh, __nv_bfloat16* __restrict__ AOl)
{
    extern __shared__ __nv_bfloat16 asmem[];
    const int tid  = threadIdx.x;
    const int lane = tid & 31;
    const int w    = tid >> 5;
    const int qt   = (int)gridDim.x - 1 - (int)blockIdx.x;
    const int h    = blockIdx.y;
    const int b    = blockIdx.z;
    const int q0   = qt * 128;
    const uint32_t sbase = smem_u32(asmem);

    {
        const float* Qb = Q + ((size_t)(b * SEQ + q0)) * DMODEL + h * DHEAD;
        #pragma unroll
        for (int i = 0; i < 8; ++i) {
            int idx = tid + i * 256;
            int row = idx >> 4, c4 = (idx & 15) * 4;
            float4 v = *reinterpret_cast<const float4*>(Qb + (size_t)row * DMODEL + c4);
            int off = row * RSA + c4;
            split_store(asmem + AT_STG + off, asmem + AT_STG + 128 * RSA + off, v);
        }
    }
    __syncthreads();
    uint32_t qh[4][4], ql[4][4];
    #pragma unroll
    for (int ks = 0; ks < 4; ++ks) {
        const uint32_t off = ((w * 16 + (lane & 15)) * RSA + ks * 16 + ((lane >> 4) << 3)) * 2;
        LDMX4(qh[ks][0], qh[ks][1], qh[ks][2], qh[ks][3], sbase + AT_STG * 2 + off);
        LDMX4(ql[ks][0], ql[ks][1], ql[ks][2], ql[ks][3], sbase + (AT_STG + 128 * RSA) * 2 + off);
    }
    __syncthreads();

    float m0 = -1e30f, m1 = -1e30f, l0 = 0.f, l1 = 0.f;
    float o[8][4];
    #pragma unroll
    for (int j = 0; j < 8; ++j)
        #pragma unroll
        for (int q = 0; q < 4; ++q) o[j][q] = 0.f;

    const int q_r0 = q0 + w * 16 + (lane >> 2);
    const int q_r1 = q_r0 + 8;
    const float* bph = bias + (size_t)h * SEQ * SEQ;
    const int nt = 2 * qt + 2;

    const int grow = tid >> 4;
    const int gc4  = (tid & 15) * 4;
    float4 kreg[4], vreg[4];

    auto load_tile = [&](int kt) {
        const int k0 = kt * 64;
        const float* Kb = K + ((size_t)(b * SEQ + k0 + grow)) * DMODEL + h * DHEAD + gc4;
        const float* Vb = V + ((size_t)(b * SEQ + k0 + grow)) * DMODEL + h * DHEAD + gc4;
        #pragma unroll
        for (int i = 0; i < 4; ++i) kreg[i] = *reinterpret_cast<const float4*>(Kb + (size_t)i * 16 * DMODEL);
        #pragma unroll
        for (int i = 0; i < 4; ++i) vreg[i] = *reinterpret_cast<const float4*>(Vb + (size_t)i * 16 * DMODEL);
    };
    auto store_tile = [&](int s) {
        __nv_bfloat16* st = asmem + s * AT_STG;
        #pragma unroll
        for (int i = 0; i < 4; ++i) {
            const int off = (grow + i * 16) * RSA + gc4;
            split_store(st + off,              st + AT_MAT + off,     kreg[i]);
            split_store(st + 2 * AT_MAT + off, st + 3 * AT_MAT + off, vreg[i]);
        }
    };

    load_tile(0);
    store_tile(0);
    __syncthreads();

    for (int kt = 0; kt < nt; ++kt) {
        const int s  = kt & 1;
        const int k0 = kt * 64;
        if (kt + 1 < nt) load_tile(kt + 1);

        const uint32_t Khu = sbase + s * AT_STG * 2;
        const uint32_t Klu = Khu + AT_MAT * 2;
        const uint32_t Vhu = Khu + 2 * AT_MAT * 2;
        const uint32_t Vlu = Khu + 3 * AT_MAT * 2;

        float sacc[8][4];
        #pragma unroll
        for (int j = 0; j < 8; ++j)
            #pragma unroll
            for (int q = 0; q < 4; ++q) sacc[j][q] = 0.f;
        #pragma unroll
        for (int ks = 0; ks < 4; ++ks) {
            #pragma unroll
            for (int bb = 0; bb < 4; ++bb) {
                const uint32_t off =
                    ((bb * 16 + (lane & 7) + ((lane >> 4) << 3)) * RSA + ks * 16 + (lane & 8)) * 2;
                uint32_t h0, h1, h2, h3, e0, e1, e2, e3;
                LDMX4(h0, h1, h2, h3, Khu + off);
                LDMX4(e0, e1, e2, e3, Klu + off);
                MMA16816_2(sacc[2 * bb],     qh[ks], h0, h1);
                MMA16816_2(sacc[2 * bb],     qh[ks], e0, e1);
                MMA16816_2(sacc[2 * bb],     ql[ks], h0, h1);
                MMA16816_2(sacc[2 * bb + 1], qh[ks], h2, h3);
                MMA16816_2(sacc[2 * bb + 1], qh[ks], e2, e3);
                MMA16816_2(sacc[2 * bb + 1], ql[ks], h2, h3);
            }
        }

        const bool mask = (kt >= 2 * qt);
        const float* r0p = bph + (size_t)q_r0 * SEQ + k0 + 2 * (lane & 3);
        const float* r1p = bph + (size_t)q_r1 * SEQ + k0 + 2 * (lane & 3);
        #pragma unroll
        for (int nf = 0; nf < 8; ++nf) {
            float2 b0 = *reinterpret_cast<const float2*>(r0p + nf * 8);
            float2 b1 = *reinterpret_cast<const float2*>(r1p + nf * 8);
            float v0 = fmaf(sacc[nf][0], 0.18033688f, b0.x * 1.4426950f);
            float v1 = fmaf(sacc[nf][1], 0.18033688f, b0.y * 1.4426950f);
            float v2 = fmaf(sacc[nf][2], 0.18033688f, b1.x * 1.4426950f);
            float v3 = fmaf(sacc[nf][3], 0.18033688f, b1.y * 1.4426950f);
            if (mask) {
                const int kc = k0 + nf * 8 + 2 * (lane & 3);
                if (kc     > q_r0) v0 = -1e30f;
                if (kc + 1 > q_r0) v1 = -1e30f;
                if (kc     > q_r1) v2 = -1e30f;
                if (kc + 1 > q_r1) v3 = -1e30f;
            }
            sacc[nf][0] = v0; sacc[nf][1] = v1; sacc[nf][2] = v2; sacc[nf][3] = v3;
        }

        float m0n = m0, m1n = m1;
        #pragma unroll
        for (int nf = 0; nf < 8; ++nf) {
            m0n = fmaxf(m0n, fmaxf(sacc[nf][0], sacc[nf][1]));
            m1n = fmaxf(m1n, fmaxf(sacc[nf][2], sacc[nf][3]));
        }
        m0n = fmaxf(m0n, __shfl_xor_sync(0xffffffffu, m0n, 1));
        m0n = fmaxf(m0n, __shfl_xor_sync(0xffffffffu, m0n, 2));
        m1n = fmaxf(m1n, __shfl_xor_sync(0xffffffffu, m1n, 1));
        m1n = fmaxf(m1n, __shfl_xor_sync(0xffffffffu, m1n, 2));
        const float c0 = exp2p(m0 - m0n), c1 = exp2p(m1 - m1n);
        m0 = m0n; m1 = m1n;
        l0 *= c0;  l1 *= c1;
        #pragma unroll
        for (int nf = 0; nf < 8; ++nf) {
            o[nf][0] *= c0; o[nf][1] *= c0;
            o[nf][2] *= c1; o[nf][3] *= c1;
        }

        uint32_t pA0[8], pA1[8], pL0[8], pL1[8];
        #pragma unroll
        for (int nf = 0; nf < 8; ++nf) {
            float p0 = exp2p(sacc[nf][0] - m0);
            float p1 = exp2p(sacc[nf][1] - m0);
            float p2 = exp2p(sacc[nf][2] - m1);
            float p3 = exp2p(sacc[nf][3] - m1);
            l0 += p0 + p1; l1 += p2 + p3;
            __nv_bfloat16 h0 = __float2bfloat16(p0), h1 = __float2bfloat16(p1);
            __nv_bfloat16 h2 = __float2bfloat16(p2), h3 = __float2bfloat16(p3);
            pA0[nf] = (uint32_t)__bfloat16_as_ushort(h0) | ((uint32_t)__bfloat16_as_ushort(h1) << 16);
            pA1[nf] = (uint32_t)__bfloat16_as_ushort(h2) | ((uint32_t)__bfloat16_as_ushort(h3) << 16);
            pL0[nf] = packbf(p0 - __bfloat162float(h0), p1 - __bfloat162float(h1));
            pL1[nf] = packbf(p2 - __bfloat162float(h2), p3 - __bfloat162float(h3));
        }

        #pragma unroll
        for (int ks = 0; ks < 4; ++ks) {
            uint32_t ah[4] = { pA0[2 * ks], pA1[2 * ks], pA0[2 * ks + 1], pA1[2 * ks + 1] };
            uint32_t al[4] = { pL0[2 * ks], pL1[2 * ks], pL0[2 * ks + 1], pL1[2 * ks + 1] };
            #pragma unroll
            for (int ng = 0; ng < 4; ++ng) {
                const uint32_t off =
                    ((ks * 16 + (lane & 7) + (lane & 8)) * RSA + ng * 16 + ((lane >> 4) << 3)) * 2;
                uint32_t h0, h1, h2, h3, e0, e1, e2, e3;
                LDMX4T(h0, h1, h2, h3, Vhu + off);
                LDMX4T(e0, e1, e2, e3, Vlu + off);
                MMA16816_2(o[2 * ng],     ah, h0, h1);
                MMA16816_2(o[2 * ng],     al, h0, h1);
                MMA16816_2(o[2 * ng],     ah, e0, e1);
                MMA16816_2(o[2 * ng + 1], ah, h2, h3);
                MMA16816_2(o[2 * ng + 1], al, h2, h3);
                MMA16816_2(o[2 * ng + 1], ah, e2, e3);
            }
        }

        if (kt + 1 < nt) store_tile((kt + 1) & 1);
        __syncthreads();
    }

    l0 += __shfl_xor_sync(0xffffffffu, l0, 1);
    l0 += __shfl_xor_sync(0xffffffffu, l0, 2);
    l1 += __shfl_xor_sync(0xffffffffu, l1, 1);
    l1 += __shfl_xor_sync(0xffffffffu, l1, 2);
    const float i0 = 1.f / l0, i1 = 1.f / l1;
    const size_t r0off = (size_t)(b * SEQ + q_r0) * DMODEL + h * DHEAD + 2 * (lane & 3);
    const size_t r1off = (size_t)(b * SEQ + q_r1) * DMODEL + h * DHEAD + 2 * (lane & 3);
    #pragma unroll
    for (int nf = 0; nf < 8; ++nf) {
        store_pair(AOh, AOl, r0off + nf * 8, o[nf][0] * i0, o[nf][1] * i0);
        store_pair(AOh, AOl, r1off + nf * 8, o[nf][2] * i1, o[nf][3] * i1);
    }
}

// ---------------------------------------------------------------------------
extern "C" void kernel_launch(void* const* d_in, const int* in_sizes, int n_in,
                              void* d_out, int out_size)
{
    const float* x     = (const float*)d_in[0];
    const float* basis = (const float*)d_in[1];
    const float* sq    = (const float*)d_in[2];
    const float* sk    = (const float*)d_in[3];
    const float* sv    = (const float*)d_in[4];
    const float* so    = (const float*)d_in[5];
    const float* bias  = (const float*)d_in[6];
    float*       out   = (float*)d_out;

    __nv_bfloat16 *Xh, *Xl, *BTh, *BTl, *Bmh, *Bml;
    __nv_bfloat16 *XBqh, *XBql, *XBkh, *XBkl, *XBvh, *XBvl;
    __nv_bfloat16 *AOh, *AOl, *O1h, *O1l;
    float *Qm, *Km, *Vm;
    cudaGetSymbolAddress((void**)&Xh,  g_Xh);  cudaGetSymbolAddress((void**)&Xl,  g_Xl);
    cudaGetSymbolAddress((void**)&BTh, g_BTh); cudaGetSymbolAddress((void**)&BTl, g_BTl);
    cudaGetSymbolAddress((void**)&Bmh, g_Bmh); cudaGetSymbolAddress((void**)&Bml, g_Bml);
    cudaGetSymbolAddress((void**)&XBqh, g_XBqh); cudaGetSymbolAddress((void**)&XBql, g_XBql);
    cudaGetSymbolAddress((void**)&XBkh, g_XBkh); cudaGetSymbolAddress((void**)&XBkl, g_XBkl);
    cudaGetSymbolAddress((void**)&XBvh, g_XBvh); cudaGetSymbolAddress((void**)&XBvl, g_XBvl);
    cudaGetSymbolAddress((void**)&AOh, g_AOh); cudaGetSymbolAddress((void**)&AOl, g_AOl);
    cudaGetSymbolAddress((void**)&O1h, g_O1h); cudaGetSymbolAddress((void**)&O1l, g_O1l);
    cudaGetSymbolAddress((void**)&Qm, g_Q);
    cudaGetSymbolAddress((void**)&Km, g_K);
    cudaGetSymbolAddress((void**)&Vm, g_V);

    cudaFuncSetAttribute(gemm_bf16x3<0>, cudaFuncAttributeMaxDynamicSharedMemorySize, SMEM_DYN);
    cudaFuncSetAttribute(gemm_bf16x3<1>, cudaFuncAttributeMaxDynamicSharedMemorySize, SMEM_DYN);
    cudaFuncSetAttribute(gemm_bf16x3<2>, cudaFuncAttributeMaxDynamicSharedMemorySize, SMEM_DYN);
    cudaFuncSetAttribute(attn_mma, cudaFuncAttributeMaxDynamicSharedMemorySize, ASMEM);

    // pre-split inputs
    split_plain<<<MROWS * DMODEL / 1024, 256>>>((const float4*)x, Xh, Xl);
    split_plain<<<DMODEL * DMODEL / 1024, 256>>>((const float4*)basis, Bmh, Bml);
    trans_split<<<dim3(32, 32), dim3(32, 8)>>>(basis, BTh, BTl);

    const dim3 gg(DMODEL / 128, MROWS / 128);
    // G1: XB = X @ basis, epilogue emits scale-fused pairs for q/k/v
    gemm_bf16x3<1><<<gg, 256, SMEM_DYN>>>(Xh, Xl, BTh, BTl, nullptr,
                                          sq, sk, sv,
                                          XBqh, XBql, XBkh, XBkl, XBvh, XBvl);
    // G2-4: Q/K/V fp32
    gemm_bf16x3<0><<<gg, 256, SMEM_DYN>>>(XBqh, XBql, Bmh, Bml, Qm,
                                          nullptr, nullptr, nullptr,
                                          nullptr, nullptr, nullptr, nullptr, nullptr, nullptr);
    gemm_bf16x3<0><<<gg, 256, SMEM_DYN>>>(XBkh, XBkl, Bmh, Bml, Km,
                                          nullptr, nullptr, nullptr,
                                          nullptr, nullptr, nullptr, nullptr, nullptr, nullptr);
    gemm_bf16x3<0><<<gg, 256, SMEM_DYN>>>(XBvh, XBvl, Bmh, Bml, Vm,
                                          nullptr, nullptr, nullptr,
                                          nullptr, nullptr, nullptr, nullptr, nullptr, nullptr);

    attn_mma<<<dim3(SEQ / 128, NHEADS, BATCH), 256, ASMEM>>>(Qm, Km, Vm, bias, AOh, AOl);

    // G5: O1 = AO @ basis, epilogue emits so-fused pair
    gemm_bf16x3<2><<<gg, 256, SMEM_DYN>>>(AOh, AOl, BTh, BTl, nullptr,
                                          so, nullptr, nullptr,
                                          O1h, O1l, nullptr, nullptr, nullptr, nullptr);
    // G6: out = O1s @ basis^T, fp32
    gemm_bf16x3<0><<<gg, 256, SMEM_DYN>>>(O1h, O1l, Bmh, Bml, out,
                                          nullptr, nullptr, nullptr,
                                          nullptr, nullptr, nullptr, nullptr, nullptr, nullptr);
}